// round 13
// baseline (speedup 1.0000x reference)
#include <cuda_runtime.h>
#include <cuda_bf16.h>
#include <mma.h>
#include <cstdint>
#include <math.h>

using namespace nvcuda;

#define B_   128
#define N_   256
#define E_   2048
#define GTOT 256   // q graphs [0,128) + c graphs [128,256)

// ---------------- device scratch (static globals: no allocs) ----------------
__device__ __nv_bfloat16 g_Xhi[GTOT * N_ * 128];   // layer1 out hi (128-d)
__device__ __nv_bfloat16 g_Xlo[GTOT * N_ * 128];
__device__ __nv_bfloat16 g_Phi[GTOT * N_ * 32];    // final emb hi (for pair mm)
__device__ __nv_bfloat16 g_Plo[GTOT * N_ * 32];
__device__ __nv_bfloat16 g_Whi[26624];             // W1|W2|W3 bf16 hi
__device__ __nv_bfloat16 g_Wlo[26624];             // W1|W2|W3 bf16 lo
__device__ float2   g_edge[GTOT * E_];         // packed (coef, src-as-float-bits)
__device__ int      g_rowptr[GTOT * 257];
__device__ float    g_invdeg[GTOT * N_];
__device__ float    g_pool[GTOT * 32];
__device__ float    g_scoresT[B_ * 16];
__device__ unsigned g_minmax[2];
__device__ int      g_hist[16];

// monotone float<->uint mapping for atomicMin/Max over signed floats
__device__ __forceinline__ unsigned encf(float f) {
    unsigned u = __float_as_uint(f);
    return (u & 0x80000000u) ? ~u : (u | 0x80000000u);
}
__device__ __forceinline__ float decf(unsigned u) {
    return (u & 0x80000000u) ? __uint_as_float(u & 0x7fffffffu)
                             : __uint_as_float(~u);
}

// pack 4 floats -> (hi uint2, lo uint2) of bf16
__device__ __forceinline__ void split4(float4 v, uint2& hq, uint2& lq) {
    __nv_bfloat16 h0 = __float2bfloat16(v.x);
    __nv_bfloat16 h1 = __float2bfloat16(v.y);
    __nv_bfloat16 h2 = __float2bfloat16(v.z);
    __nv_bfloat16 h3 = __float2bfloat16(v.w);
    __nv_bfloat16 l0 = __float2bfloat16(v.x - __bfloat162float(h0));
    __nv_bfloat16 l1 = __float2bfloat16(v.y - __bfloat162float(h1));
    __nv_bfloat16 l2 = __float2bfloat16(v.z - __bfloat162float(h2));
    __nv_bfloat16 l3 = __float2bfloat16(v.w - __bfloat162float(h3));
    __nv_bfloat162 ph01(h0, h1), ph23(h2, h3), pl01(l0, l1), pl23(l2, l3);
    hq.x = *(unsigned*)&ph01; hq.y = *(unsigned*)&ph23;
    lq.x = *(unsigned*)&pl01; lq.y = *(unsigned*)&pl23;
}
// pack 2 floats -> hi u32, lo u32 bf16x2
__device__ __forceinline__ void split2(float a, float b, unsigned& hq, unsigned& lq) {
    __nv_bfloat16 h0 = __float2bfloat16(a);
    __nv_bfloat16 h1 = __float2bfloat16(b);
    __nv_bfloat16 l0 = __float2bfloat16(a - __bfloat162float(h0));
    __nv_bfloat16 l1 = __float2bfloat16(b - __bfloat162float(h1));
    __nv_bfloat162 ph(h0, h1), pl(l0, l1);
    hq = *(unsigned*)&ph; lq = *(unsigned*)&pl;
}

// ---------------- weight conversion (one-shot) ----------------
__global__ void __launch_bounds__(256) k_cvtW(const float* __restrict__ W1,
                                              const float* __restrict__ W2,
                                              const float* __restrict__ W3) {
    int i = blockIdx.x * 256 + threadIdx.x;
    if (i >= 26624) return;
    float w = (i < 16384) ? W1[i] : (i < 24576 ? W2[i - 16384] : W3[i - 24576]);
    __nv_bfloat16 h = __float2bfloat16(w);
    g_Whi[i] = h;
    g_Wlo[i] = __float2bfloat16(w - __bfloat162float(h));
}

// ---------------- CSR build (per graph) + global init in block 0 ----------------
__global__ void __launch_bounds__(256) k_csr(const int* __restrict__ eq,
                                             const int* __restrict__ ec) {
    const int g = blockIdx.x;
    const int t = threadIdx.x;
    if (g == 0) {
        if (t == 0) { g_minmax[0] = 0xffffffffu; g_minmax[1] = 0u; }
        if (t < 16) g_hist[t] = 0;
    }
    const int* base = (g < B_) ? (eq + (size_t)g * 2 * E_)
                               : (ec + (size_t)(g - B_) * 2 * E_);
    const int* src = base;
    const int* dst = base + E_;

    __shared__ int   cnt[256];
    __shared__ int   scan[256];
    __shared__ int   off[256];
    __shared__ float dinv[256];

    cnt[t] = 0;
    __syncthreads();
    for (int e = t; e < E_; e += 256) atomicAdd(&cnt[dst[e]], 1);
    __syncthreads();

    float deg = (float)cnt[t] + 1.0f;
    dinv[t] = rsqrtf(deg);
    g_invdeg[g * N_ + t] = 1.0f / deg;

    int v = cnt[t];
    scan[t] = v;
    __syncthreads();
    for (int s = 1; s < 256; s <<= 1) {
        int add = (t >= s) ? scan[t - s] : 0;
        __syncthreads();
        scan[t] += add;
        __syncthreads();
    }
    int excl = scan[t] - v;
    off[t] = excl;
    g_rowptr[g * 257 + t] = excl;
    if (t == 0) g_rowptr[g * 257 + 256] = E_;
    __syncthreads();

    for (int e = t; e < E_; e += 256) {
        int d = dst[e];
        int s_ = src[e];
        int pos = atomicAdd(&off[d], 1);
        g_edge[g * E_ + pos] = make_float2(dinv[s_] * dinv[d], __int_as_float(s_));
    }
}

// ======================= layer 1 (unchanged R12): stage X -> wmma -> H smem -> gather agg =======================
__global__ void __launch_bounds__(512) k_fused1(
    const float* __restrict__ in0, const float* __restrict__ in1,
    const __nv_bfloat16* __restrict__ Whi_, const __nv_bfloat16* __restrict__ Wlo_,
    const float* __restrict__ bias)
{
    constexpr int K = 128, FO = 128;
    constexpr int LDA = K + 8;
    constexpr int LDB = FO + 8;
    extern __shared__ __align__(16) char smc[];
    __nv_bfloat16* Ahi = (__nv_bfloat16*)smc;          // 256*LDA
    __nv_bfloat16* Alo = Ahi + 256 * LDA;
    __nv_bfloat16* Bhi = Alo + 256 * LDA;              // K*LDB
    __nv_bfloat16* Blo = Bhi + K * LDB;
    float2* esm = (float2*)(Blo + K * LDB);            // E_
    int*    rsm = (int*)(esm + E_);                    // 258
    float*  dsm = (float*)(rsm + 258);                 // 256

    const int g = blockIdx.x;
    const int t = threadIdx.x;
    const int wid = t >> 5;

    {
        const float* X = (g < B_) ? in0 + (size_t)g * N_ * K
                                  : in1 + (size_t)(g - B_) * N_ * K;
        const float4* X4 = (const float4*)X;
        constexpr int KQ = K / 4;
        for (int i = t; i < N_ * KQ; i += 512) {
            int r = i / KQ, c = i % KQ;
            uint2 hq, lq;
            split4(X4[i], hq, lq);
            ((uint2*)(Ahi + r * LDA))[c] = hq;
            ((uint2*)(Alo + r * LDA))[c] = lq;
        }
    }
    {
        constexpr int FQ = FO / 8;
        const uint4* GH = (const uint4*)Whi_;
        const uint4* GL = (const uint4*)Wlo_;
        for (int i = t; i < K * FQ; i += 512) {
            int r = i / FQ, c = i % FQ;
            ((uint4*)(Bhi + r * LDB))[c] = GH[i];
            ((uint4*)(Blo + r * LDB))[c] = GL[i];
        }
    }
    for (int i = t; i < E_; i += 512) esm[i] = g_edge[(size_t)g * E_ + i];
    for (int i = t; i < 257; i += 512) rsm[i] = g_rowptr[g * 257 + i];
    for (int i = t; i < 256; i += 512) dsm[i] = g_invdeg[g * N_ + i];
    __syncthreads();

    constexpr int NT = FO / 16;
    wmma::fragment<wmma::accumulator, 16, 16, 16, float> C[NT];
#pragma unroll
    for (int n = 0; n < NT; n++) wmma::fill_fragment(C[n], 0.0f);

    const __nv_bfloat16* Ah = Ahi + (size_t)(wid * 16) * LDA;
    const __nv_bfloat16* Al = Alo + (size_t)(wid * 16) * LDA;
#pragma unroll
    for (int k0 = 0; k0 < K; k0 += 16) {
        wmma::fragment<wmma::matrix_a, 16, 16, 16, __nv_bfloat16, wmma::row_major> ah, al;
        wmma::load_matrix_sync(ah, Ah + k0, LDA);
        wmma::load_matrix_sync(al, Al + k0, LDA);
#pragma unroll
        for (int n = 0; n < NT; n++) {
            wmma::fragment<wmma::matrix_b, 16, 16, 16, __nv_bfloat16, wmma::row_major> bh, bl;
            wmma::load_matrix_sync(bh, Bhi + (size_t)k0 * LDB + n * 16, LDB);
            wmma::load_matrix_sync(bl, Blo + (size_t)k0 * LDB + n * 16, LDB);
            wmma::mma_sync(C[n], ah, bh, C[n]);
            wmma::mma_sync(C[n], ah, bl, C[n]);
            wmma::mma_sync(C[n], al, bh, C[n]);
        }
    }
    __syncthreads();

    float* Hs = (float*)smc;
#pragma unroll
    for (int n = 0; n < NT; n++)
        wmma::store_matrix_sync(Hs + (size_t)(wid * 16) * FO + n * 16, C[n],
                                FO, wmma::mem_row_major);
    __syncthreads();

    constexpr int QPN = FO / 4;
    constexpr int NPB = 512 / QPN;
    const int fq = t % QPN;
    const int n0 = t / QPN;
    const float4 bf = ((const float4*)bias)[fq];
    const float4* h4 = (const float4*)Hs;
    uint2* OHI = (uint2*)g_Xhi + (size_t)g * N_ * QPN;
    uint2* OLO = (uint2*)g_Xlo + (size_t)g * N_ * QPN;

    for (int n = n0; n < N_; n += NPB) {
        const int e0 = rsm[n], e1 = rsm[n + 1];
        float4 a0 = make_float4(0.f, 0.f, 0.f, 0.f);
        float4 a1 = make_float4(0.f, 0.f, 0.f, 0.f);
        int e = e0;
        for (; e + 1 < e1; e += 2) {
            float2 ed0 = esm[e];
            float2 ed1 = esm[e + 1];
            float4 h0 = h4[__float_as_int(ed0.y) * QPN + fq];
            float4 h1 = h4[__float_as_int(ed1.y) * QPN + fq];
            a0.x += h0.x * ed0.x; a0.y += h0.y * ed0.x;
            a0.z += h0.z * ed0.x; a0.w += h0.w * ed0.x;
            a1.x += h1.x * ed1.x; a1.y += h1.y * ed1.x;
            a1.z += h1.z * ed1.x; a1.w += h1.w * ed1.x;
        }
        if (e < e1) {
            float2 ed0 = esm[e];
            float4 h0 = h4[__float_as_int(ed0.y) * QPN + fq];
            a0.x += h0.x * ed0.x; a0.y += h0.y * ed0.x;
            a0.z += h0.z * ed0.x; a0.w += h0.w * ed0.x;
        }
        const float id = dsm[n];
        float4 hs = h4[n * QPN + fq];
        float4 v;
        v.x = fmaxf(a0.x + a1.x + hs.x * id + bf.x, 0.f);
        v.y = fmaxf(a0.y + a1.y + hs.y * id + bf.y, 0.f);
        v.z = fmaxf(a0.z + a1.z + hs.z * id + bf.z, 0.f);
        v.w = fmaxf(a0.w + a1.w + hs.w * id + bf.w, 0.f);
        uint2 hq, lq;
        split4(v, hq, lq);
        OHI[n * QPN + fq] = hq;
        OLO[n * QPN + fq] = lq;
    }
}

// ======================= layers 2+3 + pooling: aggregation as P@H tensor GEMM =======================
// smem (206,344 B):
//   [0,139264)        dynamic region (A2hl / H2f / P / A3f / H3f / Es overlays)
//   [139264,176128)   W2 hi/lo (LDB2=72)
//   [176128,186368)   W3 hi/lo (LDB3=40)
//   [186368,202752)   edges (E_ float2, dst-sorted)
//   [202752,203784)   rowptr
//   [203784,204808)   invdeg
//   [204808,206344)   pool scratch
__global__ void __launch_bounds__(512) k_fused23(
    const __nv_bfloat16* __restrict__ W2hi_, const __nv_bfloat16* __restrict__ W2lo_,
    const __nv_bfloat16* __restrict__ W3hi_, const __nv_bfloat16* __restrict__ W3lo_,
    const float* __restrict__ b2, const float* __restrict__ b3,
    const float* __restrict__ Watt)
{
    constexpr int LDA2 = 136, LDB2 = 72, LDB3 = 40;
    constexpr int LDP = 40;   // P chunk: 256 x 32 (+8 pad)
    extern __shared__ __align__(16) char smc[];
    __nv_bfloat16* W2hi = (__nv_bfloat16*)(smc + 139264);
    __nv_bfloat16* W2lo = W2hi + 128 * LDB2;
    __nv_bfloat16* W3hi = W2lo + 128 * LDB2;
    __nv_bfloat16* W3lo = W3hi + 64 * LDB3;
    float2* esm = (float2*)(smc + 186368);
    int*    rsm = (int*)(smc + 202752);
    float*  dsm = (float*)(smc + 203784);
    float*  colsum = (float*)(smc + 204808);
    float*  ctx    = colsum + 32;
    float*  score  = ctx + 32;

    const int g = blockIdx.x;
    const int t = threadIdx.x;
    const int wid = t >> 5;

    // ---- stage A2 hi/lo, W2, W3, edges ----
    {
        __nv_bfloat16* A2hi = (__nv_bfloat16*)smc;
        __nv_bfloat16* A2lo = A2hi + 256 * LDA2;
        const uint4* GH = (const uint4*)(g_Xhi + (size_t)g * N_ * 128);
        const uint4* GL = (const uint4*)(g_Xlo + (size_t)g * N_ * 128);
        for (int i = t; i < N_ * 16; i += 512) {
            int r = i / 16, c = i % 16;
            ((uint4*)(A2hi + r * LDA2))[c] = GH[i];
            ((uint4*)(A2lo + r * LDA2))[c] = GL[i];
        }
        const uint4* WH = (const uint4*)W2hi_;
        const uint4* WL = (const uint4*)W2lo_;
        for (int i = t; i < 128 * 8; i += 512) {
            int r = i / 8, c = i % 8;
            ((uint4*)(W2hi + r * LDB2))[c] = WH[i];
            ((uint4*)(W2lo + r * LDB2))[c] = WL[i];
        }
        const uint4* WH3 = (const uint4*)W3hi_;
        const uint4* WL3 = (const uint4*)W3lo_;
        for (int i = t; i < 64 * 4; i += 512) {
            int r = i / 4, c = i % 4;
            ((uint4*)(W3hi + r * LDB3))[c] = WH3[i];
            ((uint4*)(W3lo + r * LDB3))[c] = WL3[i];
        }
    }
    for (int i = t; i < E_; i += 512) esm[i] = g_edge[(size_t)g * E_ + i];
    for (int i = t; i < 257; i += 512) rsm[i] = g_rowptr[g * 257 + i];
    for (int i = t; i < 256; i += 512) dsm[i] = g_invdeg[g * N_ + i];
    __syncthreads();

    // ======== GEMM2: H2 = A2 @ W2 (FO=64, NT=4) ========
    {
        __nv_bfloat16* A2hi = (__nv_bfloat16*)smc;
        __nv_bfloat16* A2lo = A2hi + 256 * LDA2;
        wmma::fragment<wmma::accumulator, 16, 16, 16, float> C[4];
#pragma unroll
        for (int n = 0; n < 4; n++) wmma::fill_fragment(C[n], 0.0f);
        const __nv_bfloat16* Ah = A2hi + (size_t)(wid * 16) * LDA2;
        const __nv_bfloat16* Al = A2lo + (size_t)(wid * 16) * LDA2;
#pragma unroll
        for (int k0 = 0; k0 < 128; k0 += 16) {
            wmma::fragment<wmma::matrix_a, 16, 16, 16, __nv_bfloat16, wmma::row_major> ah, al;
            wmma::load_matrix_sync(ah, Ah + k0, LDA2);
            wmma::load_matrix_sync(al, Al + k0, LDA2);
#pragma unroll
            for (int n = 0; n < 4; n++) {
                wmma::fragment<wmma::matrix_b, 16, 16, 16, __nv_bfloat16, wmma::row_major> bh, bl;
                wmma::load_matrix_sync(bh, W2hi + (size_t)k0 * LDB2 + n * 16, LDB2);
                wmma::load_matrix_sync(bl, W2lo + (size_t)k0 * LDB2 + n * 16, LDB2);
                wmma::mma_sync(C[n], ah, bh, C[n]);
                wmma::mma_sync(C[n], ah, bl, C[n]);
                wmma::mma_sync(C[n], al, bh, C[n]);
            }
        }
        __syncthreads();   // A2 dead -> H2f at [0,64K)
        float* H2f = (float*)smc;
#pragma unroll
        for (int n = 0; n < 4; n++)
            wmma::store_matrix_sync(H2f + (size_t)(wid * 16) * 64 + n * 16, C[n],
                                    64, wmma::mem_row_major);
        __syncthreads();
    }

    // ---- convert H2f -> H2 hi/lo planes at [65536, 139264) ----
    {
        const float* H2f = (const float*)smc;
        unsigned* Hhi = (unsigned*)(smc + 65536);   // 256 x 72 bf16, as u32 pairs
        unsigned* Hlo = (unsigned*)(smc + 102400);
        for (int i = t; i < 256 * 32; i += 512) {   // pairs
            int d = i / 32, fp = i % 32;
            float a = H2f[d * 64 + fp * 2], b = H2f[d * 64 + fp * 2 + 1];
            unsigned hq, lq;
            split2(a, b, hq, lq);
            Hhi[d * 36 + fp] = hq;                  // 72/2 = 36 u32 per row
            Hlo[d * 36 + fp] = lq;
        }
        __syncthreads();
    }

    // ======== agg2: A3' = P @ H2 (chunked P, NT=4) ========
    {
        wmma::fragment<wmma::accumulator, 16, 16, 16, float> C[4];
#pragma unroll
        for (int n = 0; n < 4; n++) wmma::fill_fragment(C[n], 0.0f);
        float* Pst = (float*)smc;                          // [0,32K)
        __nv_bfloat16* Phs = (__nv_bfloat16*)smc;          // hi plane [0,20480)
        __nv_bfloat16* Pls = (__nv_bfloat16*)(smc + 20480);
        const __nv_bfloat16* Hhi = (const __nv_bfloat16*)(smc + 65536);
        const __nv_bfloat16* Hlo = (const __nv_bfloat16*)(smc + 102400);

        for (int kc = 0; kc < 8; kc++) {
            const int base = kc * 32;
            for (int i = t; i < 256 * 32; i += 512) Pst[i] = 0.f;
            __syncthreads();
            if (t < 256) {
                const int d = t;
                for (int e = rsm[d]; e < rsm[d + 1]; e++) {
                    float2 ed = esm[e];
                    int s = __float_as_int(ed.y) - base;
                    if ((unsigned)s < 32u) Pst[d * 32 + s] += ed.x;
                }
                int sd = d - base;
                if ((unsigned)sd < 32u) Pst[d * 32 + sd] += dsm[d];
            }
            __syncthreads();
            float pv[16];
#pragma unroll
            for (int j = 0; j < 16; j++) pv[j] = Pst[t * 16 + j];
            __syncthreads();
#pragma unroll
            for (int j = 0; j < 8; j++) {
                int li = t * 16 + j * 2;
                int d = li / 32, s = li % 32;
                unsigned hq, lq;
                split2(pv[j * 2], pv[j * 2 + 1], hq, lq);
                ((unsigned*)(Phs + d * LDP))[s / 2] = hq;
                ((unsigned*)(Pls + d * LDP))[s / 2] = lq;
            }
            __syncthreads();
            const __nv_bfloat16* Pa = Phs + (size_t)(wid * 16) * LDP;
            const __nv_bfloat16* Pb = Pls + (size_t)(wid * 16) * LDP;
#pragma unroll
            for (int kt = 0; kt < 2; kt++) {
                wmma::fragment<wmma::matrix_a, 16, 16, 16, __nv_bfloat16, wmma::row_major> ph, pl;
                wmma::load_matrix_sync(ph, Pa + kt * 16, LDP);
                wmma::load_matrix_sync(pl, Pb + kt * 16, LDP);
                const int row = base + kt * 16;
#pragma unroll
                for (int n = 0; n < 4; n++) {
                    wmma::fragment<wmma::matrix_b, 16, 16, 16, __nv_bfloat16, wmma::row_major> hh, hl;
                    wmma::load_matrix_sync(hh, Hhi + (size_t)row * LDB2 + n * 16, LDB2);
                    wmma::load_matrix_sync(hl, Hlo + (size_t)row * LDB2 + n * 16, LDB2);
                    wmma::mma_sync(C[n], ph, hh, C[n]);
                    wmma::mma_sync(C[n], ph, hl, C[n]);
                    wmma::mma_sync(C[n], pl, hh, C[n]);
                }
            }
            __syncthreads();
        }
        float* A3f = (float*)smc;   // [0,64K); P region dead
#pragma unroll
        for (int n = 0; n < 4; n++)
            wmma::store_matrix_sync(A3f + (size_t)(wid * 16) * 64 + n * 16, C[n],
                                    64, wmma::mem_row_major);
        __syncthreads();
    }

    // ---- bias + relu + split A3f -> A3 hi/lo planes at [65536,139264) ----
    {
        const float* A3f = (const float*)smc;
        unsigned* Ahi = (unsigned*)(smc + 65536);   // 256 x 72
        unsigned* Alo = (unsigned*)(smc + 102400);
        for (int i = t; i < 256 * 32; i += 512) {
            int d = i / 32, fp = i % 32;
            float a = fmaxf(A3f[d * 64 + fp * 2]     + b2[fp * 2], 0.f);
            float b = fmaxf(A3f[d * 64 + fp * 2 + 1] + b2[fp * 2 + 1], 0.f);
            unsigned hq, lq;
            split2(a, b, hq, lq);
            Ahi[d * 36 + fp] = hq;
            Alo[d * 36 + fp] = lq;
        }
        __syncthreads();
    }

    // ======== GEMM3: H3 = A3 @ W3 (K=64, FO=32, NT=2) ========
    {
        const __nv_bfloat16* A3hi = (const __nv_bfloat16*)(smc + 65536);
        const __nv_bfloat16* A3lo = (const __nv_bfloat16*)(smc + 102400);
        wmma::fragment<wmma::accumulator, 16, 16, 16, float> C[2];
#pragma unroll
        for (int n = 0; n < 2; n++) wmma::fill_fragment(C[n], 0.0f);
        const __nv_bfloat16* Ah = A3hi + (size_t)(wid * 16) * LDB2;
        const __nv_bfloat16* Al = A3lo + (size_t)(wid * 16) * LDB2;
#pragma unroll
        for (int k0 = 0; k0 < 64; k0 += 16) {
            wmma::fragment<wmma::matrix_a, 16, 16, 16, __nv_bfloat16, wmma::row_major> ah, al;
            wmma::load_matrix_sync(ah, Ah + k0, LDB2);
            wmma::load_matrix_sync(al, Al + k0, LDB2);
#pragma unroll
            for (int n = 0; n < 2; n++) {
                wmma::fragment<wmma::matrix_b, 16, 16, 16, __nv_bfloat16, wmma::row_major> bh, bl;
                wmma::load_matrix_sync(bh, W3hi + (size_t)k0 * LDB3 + n * 16, LDB3);
                wmma::load_matrix_sync(bl, W3lo + (size_t)k0 * LDB3 + n * 16, LDB3);
                wmma::mma_sync(C[n], ah, bh, C[n]);
                wmma::mma_sync(C[n], ah, bl, C[n]);
                wmma::mma_sync(C[n], al, bh, C[n]);
            }
        }
        __syncthreads();
        float* H3f = (float*)smc;   // [0,32K)
#pragma unroll
        for (int n = 0; n < 2; n++)
            wmma::store_matrix_sync(H3f + (size_t)(wid * 16) * 32 + n * 16, C[n],
                                    32, wmma::mem_row_major);
        __syncthreads();
    }

    // ---- convert H3f -> H3 hi/lo planes at [32768,73728) ----
    {
        const float* H3f = (const float*)smc;
        unsigned* Hhi = (unsigned*)(smc + 32768);   // 256 x 40
        unsigned* Hlo = (unsigned*)(smc + 53248);
        for (int i = t; i < 256 * 16; i += 512) {
            int d = i / 16, fp = i % 16;
            unsigned hq, lq;
            split2(H3f[d * 32 + fp * 2], H3f[d * 32 + fp * 2 + 1], hq, lq);
            Hhi[d * 20 + fp] = hq;                  // 40/2 = 20 u32 per row
            Hlo[d * 20 + fp] = lq;
        }
        __syncthreads();
    }

    // ======== agg3: E' = P @ H3 (NT=2), P region at [73728,114688) ========
    {
        wmma::fragment<wmma::accumulator, 16, 16, 16, float> C[2];
#pragma unroll
        for (int n = 0; n < 2; n++) wmma::fill_fragment(C[n], 0.0f);
        float* Pst = (float*)(smc + 73728);
        __nv_bfloat16* Phs = (__nv_bfloat16*)(smc + 73728);
        __nv_bfloat16* Pls = (__nv_bfloat16*)(smc + 94208);
        const __nv_bfloat16* Hhi = (const __nv_bfloat16*)(smc + 32768);
        const __nv_bfloat16* Hlo = (const __nv_bfloat16*)(smc + 53248);

        for (int kc = 0; kc < 8; kc++) {
            const int base = kc * 32;
            for (int i = t; i < 256 * 32; i += 512) Pst[i] = 0.f;
            __syncthreads();
            if (t < 256) {
                const int d = t;
                for (int e = rsm[d]; e < rsm[d + 1]; e++) {
                    float2 ed = esm[e];
                    int s = __float_as_int(ed.y) - base;
                    if ((unsigned)s < 32u) Pst[d * 32 + s] += ed.x;
                }
                int sd = d - base;
                if ((unsigned)sd < 32u) Pst[d * 32 + sd] += dsm[d];
            }
            __syncthreads();
            float pv[16];
#pragma unroll
            for (int j = 0; j < 16; j++) pv[j] = Pst[t * 16 + j];
            __syncthreads();
#pragma unroll
            for (int j = 0; j < 8; j++) {
                int li = t * 16 + j * 2;
                int d = li / 32, s = li % 32;
                unsigned hq, lq;
                split2(pv[j * 2], pv[j * 2 + 1], hq, lq);
                ((unsigned*)(Phs + d * LDP))[s / 2] = hq;
                ((unsigned*)(Pls + d * LDP))[s / 2] = lq;
            }
            __syncthreads();
            const __nv_bfloat16* Pa = Phs + (size_t)(wid * 16) * LDP;
            const __nv_bfloat16* Pb = Pls + (size_t)(wid * 16) * LDP;
#pragma unroll
            for (int kt = 0; kt < 2; kt++) {
                wmma::fragment<wmma::matrix_a, 16, 16, 16, __nv_bfloat16, wmma::row_major> ph, pl;
                wmma::load_matrix_sync(ph, Pa + kt * 16, LDP);
                wmma::load_matrix_sync(pl, Pb + kt * 16, LDP);
                const int row = base + kt * 16;
#pragma unroll
                for (int n = 0; n < 2; n++) {
                    wmma::fragment<wmma::matrix_b, 16, 16, 16, __nv_bfloat16, wmma::row_major> hh, hl;
                    wmma::load_matrix_sync(hh, Hhi + (size_t)row * LDB3 + n * 16, LDB3);
                    wmma::load_matrix_sync(hl, Hlo + (size_t)row * LDB3 + n * 16, LDB3);
                    wmma::mma_sync(C[n], ph, hh, C[n]);
                    wmma::mma_sync(C[n], ph, hl, C[n]);
                    wmma::mma_sync(C[n], pl, hh, C[n]);
                }
            }
            __syncthreads();
        }
        float* Esf = (float*)smc;   // [0,32K); H3f dead
#pragma unroll
        for (int n = 0; n < 2; n++)
            wmma::store_matrix_sync(Esf + (size_t)(wid * 16) * 32 + n * 16, C[n],
                                    32, wmma::mem_row_major);
        __syncthreads();
    }

    // ---- bias + split -> Es (in-place) + Phi/Plo global ----
    {
        float* Esf = (float*)smc;
        unsigned* PHI = (unsigned*)g_Phi + (size_t)g * N_ * 16;
        unsigned* PLO = (unsigned*)g_Plo + (size_t)g * N_ * 16;
        for (int i = t; i < 256 * 16; i += 512) {
            int d = i / 16, fp = i % 16;
            float a = Esf[d * 32 + fp * 2]     + b3[fp * 2];
            float b = Esf[d * 32 + fp * 2 + 1] + b3[fp * 2 + 1];
            Esf[d * 32 + fp * 2] = a;
            Esf[d * 32 + fp * 2 + 1] = b;
            unsigned hq, lq;
            split2(a, b, hq, lq);
            PHI[d * 16 + fp] = hq;
            PLO[d * 16 + fp] = lq;
        }
        __syncthreads();
    }

    // ======== attention pooling (from Esf in smem) ========
    {
        const float* Es = (const float*)smc;
        if (t < 32) {
            float s = 0.f;
            for (int n = 0; n < N_; n++) s += Es[n * 32 + t];
            colsum[t] = s;
        }
        __syncthreads();
        if (t < 32) {
            float a = 0.f;
            for (int i = 0; i < 32; i++) a += colsum[i] * Watt[t * 32 + i];
            ctx[t] = tanhf(a * (1.0f / 256.0f));
        }
        __syncthreads();
        if (t < 256) {
            const int lane = t & 31;
            float d = 0.f;
#pragma unroll
            for (int j = 0; j < 32; j++) {
                int i = (lane + j) & 31;
                d += Es[t * 32 + i] * ctx[i];
            }
            score[t] = 1.0f / (1.0f + expf(-d));
        }
        __syncthreads();
        if (t < 32) {
            float s = 0.f;
            for (int n = 0; n < N_; n++) s += Es[n * 32 + t] * score[n];
            g_pool[g * 32 + t] = s;
        }
    }
}

// ---------------- NTN ----------------
__global__ void __launch_bounds__(512) k_ntn(const float* __restrict__ ntnW,
                                             const float* __restrict__ ntnV,
                                             const float* __restrict__ ntnb) {
    const int b = blockIdx.x;
    __shared__ float e1[32], e2[32];
    const int t = threadIdx.x;
    if (t < 32)      e1[t]      = g_pool[b * 32 + t];
    else if (t < 64) e2[t - 32] = g_pool[(B_ + b) * 32 + (t - 32)];
    __syncthreads();

    const int w = t >> 5, lane = t & 31;
    const float* Wt = ntnW + w * 1024;
    float a = 0.f;
#pragma unroll 8
    for (int j = 0; j < 32; j++) a += Wt[lane * 32 + j] * e2[j];
    float partial = e1[lane] * a
                  + e1[lane] * ntnV[w * 64 + lane]
                  + e2[lane] * ntnV[w * 64 + 32 + lane];
#pragma unroll
    for (int o = 16; o; o >>= 1)
        partial += __shfl_xor_sync(0xffffffffu, partial, o);
    if (lane == 0)
        g_scoresT[b * 16 + w] = fmaxf(partial + ntnb[w], 0.f);
}

// ============ pair matrix: shared staging + split-bf16 wmma tile compute ============
template<typename F>
__device__ __forceinline__ void pair_tiles(int half, int b, int t, F&& consume) {
    constexpr int LD = 40;
    __shared__ __align__(16) __nv_bfloat16 Qh[128 * LD];
    __shared__ __align__(16) __nv_bfloat16 Ql[128 * LD];
    __shared__ __align__(16) __nv_bfloat16 Ch[256 * LD];
    __shared__ __align__(16) __nv_bfloat16 Cl[256 * LD];

    const int wid = t >> 5;

    {
        const uint4* QH = (const uint4*)(g_Phi + ((size_t)b * N_ + half * 128) * 32);
        const uint4* QL = (const uint4*)(g_Plo + ((size_t)b * N_ + half * 128) * 32);
        for (int i = t; i < 128 * 4; i += 256) {
            int r = i / 4, c = i % 4;
            ((uint4*)(Qh + r * LD))[c] = QH[i];
            ((uint4*)(Ql + r * LD))[c] = QL[i];
        }
        const uint4* CH = (const uint4*)(g_Phi + (size_t)(B_ + b) * N_ * 32);
        const uint4* CL = (const uint4*)(g_Plo + (size_t)(B_ + b) * N_ * 32);
        for (int i = t; i < 256 * 4; i += 256) {
            int r = i / 4, c = i % 4;
            ((uint4*)(Ch + r * LD))[c] = CH[i];
            ((uint4*)(Cl + r * LD))[c] = CL[i];
        }
    }
    __syncthreads();

    wmma::fragment<wmma::matrix_a, 16, 16, 16, __nv_bfloat16, wmma::row_major> ah[2], al[2];
#pragma unroll
    for (int kt = 0; kt < 2; kt++) {
        wmma::load_matrix_sync(ah[kt], Qh + (size_t)(wid * 16) * LD + kt * 16, LD);
        wmma::load_matrix_sync(al[kt], Ql + (size_t)(wid * 16) * LD + kt * 16, LD);
    }

#pragma unroll
    for (int ct = 0; ct < 16; ct++) {
        wmma::fragment<wmma::accumulator, 16, 16, 16, float> acc;
        wmma::fill_fragment(acc, 0.0f);
#pragma unroll
        for (int kt = 0; kt < 2; kt++) {
            wmma::fragment<wmma::matrix_b, 16, 16, 16, __nv_bfloat16, wmma::col_major> bh, bl;
            wmma::load_matrix_sync(bh, Ch + (size_t)(ct * 16) * LD + kt * 16, LD);
            wmma::load_matrix_sync(bl, Cl + (size_t)(ct * 16) * LD + kt * 16, LD);
            wmma::mma_sync(acc, ah[kt], bh, acc);
            wmma::mma_sync(acc, ah[kt], bl, acc);
            wmma::mma_sync(acc, al[kt], bh, acc);
        }
        consume(acc);
    }
}

// ---- pass 1: global min/max only ----
__global__ void __launch_bounds__(256) k_pair_minmax() {
    __shared__ float wmn[8], wmx[8];
    const int half = blockIdx.x, b = blockIdx.y;
    const int t = threadIdx.x, wid = t >> 5, lane = t & 31;

    float vmin = 3.402823466e38f, vmax = -3.402823466e38f;
    pair_tiles(half, b, t,
        [&](wmma::fragment<wmma::accumulator, 16, 16, 16, float>& acc) {
#pragma unroll
            for (int i = 0; i < acc.num_elements; i++) {
                vmin = fminf(vmin, acc.x[i]);
                vmax = fmaxf(vmax, acc.x[i]);
            }
        });

#pragma unroll
    for (int o = 16; o; o >>= 1) {
        vmin = fminf(vmin, __shfl_xor_sync(0xffffffffu, vmin, o));
        vmax = fmaxf(vmax, __shfl_xor_sync(0xffffffffu, vmax, o));
    }
    if (lane == 0) { wmn[wid] = vmin; wmx[wid] = vmax; }
    __syncthreads();
    if (t == 0) {
        float m = wmn[0], M = wmx[0];
        for (int i = 1; i < 8; i++) { m = fminf(m, wmn[i]); M = fmaxf(M, wmx[i]); }
        atomicMin(&g_minmax[0], encf(m));
        atomicMax(&g_minmax[1], encf(M));
    }
}

// ---- pass 2: recompute identical tiles, histogram directly ----
__global__ void __launch_bounds__(256) k_pair_hist() {
    __shared__ int hsm[8][16];
    const int half = blockIdx.x, b = blockIdx.y;
    const int t = threadIdx.x, wid = t >> 5;

    if ((t & 31) < 16) hsm[wid][t & 15] = 0;
    __syncthreads();

    const float lo = decf(g_minmax[0]);
    const float inv = 16.0f / (decf(g_minmax[1]) - lo);
    int* myh = hsm[wid];

    pair_tiles(half, b, t,
        [&](wmma::fragment<wmma::accumulator, 16, 16, 16, float>& acc) {
#pragma unroll
            for (int i = 0; i < acc.num_elements; i++) {
                int bi = (int)floorf((acc.x[i] - lo) * inv);
                bi = bi < 0 ? 0 : (bi > 15 ? 15 : bi);
                atomicAdd(&myh[bi], 1);
            }
        });

    __syncthreads();
    if (t < 16) {
        int s = 0;
#pragma unroll
        for (int w = 0; w < 8; w++) s += hsm[w][t];
        atomicAdd(&g_hist[t], s);
    }
}

// ---------------- final MLP head ----------------
__global__ void k_final(const float* __restrict__ fc1W, const float* __restrict__ fc1b,
                        const float* __restrict__ fc2W, const float* __restrict__ fc2b,
                        float* __restrict__ out) {
    __shared__ float h[16];
    const int b = threadIdx.x;
    if (b < 16) h[b] = (float)g_hist[b] * (1.0f / 8388608.0f);
    __syncthreads();

    float sc[16];
#pragma unroll
    for (int t = 0; t < 16; t++) sc[t] = g_scoresT[b * 16 + t];

    float p = fc2b[0];
#pragma unroll
    for (int j = 0; j < 16; j++) {
        float a = fc1b[j];
#pragma unroll
        for (int t = 0; t < 16; t++) a += sc[t] * fc1W[j * 32 + t];
#pragma unroll
        for (int k = 0; k < 16; k++) a += h[k] * fc1W[j * 32 + 16 + k];
        p += fmaxf(a, 0.f) * fc2W[j];
    }
    out[b] = 1.0f / (1.0f + expf(-p));
}

// ---------------- launch ----------------
extern "C" void kernel_launch(void* const* d_in, const int* in_sizes, int n_in,
                              void* d_out, int out_size) {
    const float* xq   = (const float*)d_in[0];
    const float* xc   = (const float*)d_in[1];
    const int*   eq   = (const int*)d_in[2];
    const int*   ec   = (const int*)d_in[3];
    const float* W1   = (const float*)d_in[4];
    const float* b1   = (const float*)d_in[5];
    const float* W2   = (const float*)d_in[6];
    const float* b2   = (const float*)d_in[7];
    const float* W3   = (const float*)d_in[8];
    const float* b3   = (const float*)d_in[9];
    const float* Watt = (const float*)d_in[10];
    const float* ntnW = (const float*)d_in[11];
    const float* ntnV = (const float*)d_in[12];
    const float* ntnb = (const float*)d_in[13];
    const float* fc1W = (const float*)d_in[14];
    const float* fc1b = (const float*)d_in[15];
    const float* fc2W = (const float*)d_in[16];
    const float* fc2b = (const float*)d_in[17];
    float* out = (float*)d_out;

    __nv_bfloat16 *Whi, *Wlo;
    cudaGetSymbolAddress((void**)&Whi, g_Whi);
    cudaGetSymbolAddress((void**)&Wlo, g_Wlo);

    constexpr int EDGE = E_ * 8 + 258 * 4 + 256 * 4;                 // 18,440
    constexpr int SMF1  = (2 * 256 * 136 + 2 * 128 * 136) * 2 + EDGE; // 227,336
    constexpr int SMF23 = 139264 + 47104 + EDGE + 1536;               // 206,344

    cudaFuncSetAttribute(k_fused1,  cudaFuncAttributeMaxDynamicSharedMemorySize, SMF1);
    cudaFuncSetAttribute(k_fused23, cudaFuncAttributeMaxDynamicSharedMemorySize, SMF23);

    k_csr<<<GTOT, 256>>>(eq, ec);
    k_cvtW<<<104, 256>>>(W1, W2, W3);

    k_fused1<<<GTOT, 512, SMF1>>>(xq, xc, Whi, Wlo, b1);
    k_fused23<<<GTOT, 512, SMF23>>>(Whi + 16384, Wlo + 16384,
                                    Whi + 24576, Wlo + 24576, b2, b3, Watt);

    k_ntn<<<B_, 512>>>(ntnW, ntnV, ntnb);

    k_pair_minmax<<<dim3(2, B_), 256>>>();
    k_pair_hist<<<dim3(2, B_), 256>>>();

    k_final<<<1, B_>>>(fc1W, fc1b, fc2W, fc2b, out);
}

// round 15
// speedup vs baseline: 1.7821x; 1.7821x over previous
#include <cuda_runtime.h>
#include <cuda_bf16.h>
#include <mma.h>
#include <cstdint>
#include <math.h>

using namespace nvcuda;

#define B_   128
#define N_   256
#define E_   2048
#define GTOT 256   // q graphs [0,128) + c graphs [128,256)

// ---------------- device scratch (static globals: no allocs) ----------------
__device__ __nv_bfloat16 g_Xhi[GTOT * N_ * 128];   // layer1 out hi (128-d)
__device__ __nv_bfloat16 g_Xlo[GTOT * N_ * 128];
__device__ __nv_bfloat16 g_Phi[GTOT * N_ * 32];    // final emb hi (for pair mm)
__device__ __nv_bfloat16 g_Plo[GTOT * N_ * 32];
__device__ __nv_bfloat16 g_Whi[26624];             // W1|W2|W3 bf16 hi
__device__ __nv_bfloat16 g_Wlo[26624];             // W1|W2|W3 bf16 lo
__device__ float2   g_edge[GTOT * E_];         // packed (coef, src-as-float-bits)
__device__ int      g_rowptr[GTOT * 257];
__device__ float    g_invdeg[GTOT * N_];
__device__ float    g_pool[GTOT * 32];
__device__ float    g_scoresT[B_ * 16];
__device__ unsigned g_minmax[2];
__device__ int      g_hist[16];

// monotone float<->uint mapping for atomicMin/Max over signed floats
__device__ __forceinline__ unsigned encf(float f) {
    unsigned u = __float_as_uint(f);
    return (u & 0x80000000u) ? ~u : (u | 0x80000000u);
}
__device__ __forceinline__ float decf(unsigned u) {
    return (u & 0x80000000u) ? __uint_as_float(u & 0x7fffffffu)
                             : __uint_as_float(~u);
}

// pack 4 floats -> (hi uint2, lo uint2) of bf16
__device__ __forceinline__ void split4(float4 v, uint2& hq, uint2& lq) {
    __nv_bfloat16 h0 = __float2bfloat16(v.x);
    __nv_bfloat16 h1 = __float2bfloat16(v.y);
    __nv_bfloat16 h2 = __float2bfloat16(v.z);
    __nv_bfloat16 h3 = __float2bfloat16(v.w);
    __nv_bfloat16 l0 = __float2bfloat16(v.x - __bfloat162float(h0));
    __nv_bfloat16 l1 = __float2bfloat16(v.y - __bfloat162float(h1));
    __nv_bfloat16 l2 = __float2bfloat16(v.z - __bfloat162float(h2));
    __nv_bfloat16 l3 = __float2bfloat16(v.w - __bfloat162float(h3));
    __nv_bfloat162 ph01(h0, h1), ph23(h2, h3), pl01(l0, l1), pl23(l2, l3);
    hq.x = *(unsigned*)&ph01; hq.y = *(unsigned*)&ph23;
    lq.x = *(unsigned*)&pl01; lq.y = *(unsigned*)&pl23;
}

// ---------------- CSR build (per graph) + W conversion + global init ----------------
__global__ void __launch_bounds__(256) k_csr(const int* __restrict__ eq,
                                             const int* __restrict__ ec,
                                             const float* __restrict__ W1,
                                             const float* __restrict__ W2,
                                             const float* __restrict__ W3) {
    const int g = blockIdx.x;
    const int t = threadIdx.x;
    if (g == 0) {
        if (t == 0) { g_minmax[0] = 0xffffffffu; g_minmax[1] = 0u; }
        if (t < 16) g_hist[t] = 0;
    }
    // fold weight conversion into the first 104 blocks
    {
        int wi = g * 256 + t;
        if (wi < 26624) {
            float w = (wi < 16384) ? W1[wi]
                    : (wi < 24576 ? W2[wi - 16384] : W3[wi - 24576]);
            __nv_bfloat16 h = __float2bfloat16(w);
            g_Whi[wi] = h;
            g_Wlo[wi] = __float2bfloat16(w - __bfloat162float(h));
        }
    }
    const int* base = (g < B_) ? (eq + (size_t)g * 2 * E_)
                               : (ec + (size_t)(g - B_) * 2 * E_);
    const int* src = base;
    const int* dst = base + E_;

    __shared__ int   cnt[256];
    __shared__ int   scan[256];
    __shared__ int   off[256];
    __shared__ float dinv[256];

    cnt[t] = 0;
    __syncthreads();
    for (int e = t; e < E_; e += 256) atomicAdd(&cnt[dst[e]], 1);
    __syncthreads();

    float deg = (float)cnt[t] + 1.0f;
    dinv[t] = rsqrtf(deg);
    g_invdeg[g * N_ + t] = 1.0f / deg;

    int v = cnt[t];
    scan[t] = v;
    __syncthreads();
    for (int s = 1; s < 256; s <<= 1) {
        int add = (t >= s) ? scan[t - s] : 0;
        __syncthreads();
        scan[t] += add;
        __syncthreads();
    }
    int excl = scan[t] - v;
    off[t] = excl;
    g_rowptr[g * 257 + t] = excl;
    if (t == 0) g_rowptr[g * 257 + 256] = E_;
    __syncthreads();

    for (int e = t; e < E_; e += 256) {
        int d = dst[e];
        int s_ = src[e];
        int pos = atomicAdd(&off[d], 1);
        g_edge[g * E_ + pos] = make_float2(dinv[s_] * dinv[d], __int_as_float(s_));
    }
}

// ======================= layer 1: stage X -> wmma -> H smem -> gather agg =======================
__global__ void __launch_bounds__(512) k_fused1(
    const float* __restrict__ in0, const float* __restrict__ in1,
    const __nv_bfloat16* __restrict__ Whi_, const __nv_bfloat16* __restrict__ Wlo_,
    const float* __restrict__ bias)
{
    constexpr int K = 128, FO = 128;
    constexpr int LDA = K + 8;
    constexpr int LDB = FO + 8;
    extern __shared__ __align__(16) char smc[];
    __nv_bfloat16* Ahi = (__nv_bfloat16*)smc;          // 256*LDA
    __nv_bfloat16* Alo = Ahi + 256 * LDA;
    __nv_bfloat16* Bhi = Alo + 256 * LDA;              // K*LDB
    __nv_bfloat16* Blo = Bhi + K * LDB;
    float2* esm = (float2*)(Blo + K * LDB);            // E_
    int*    rsm = (int*)(esm + E_);                    // 258
    float*  dsm = (float*)(rsm + 258);                 // 256

    const int g = blockIdx.x;
    const int t = threadIdx.x;
    const int wid = t >> 5;

    {
        const float* X = (g < B_) ? in0 + (size_t)g * N_ * K
                                  : in1 + (size_t)(g - B_) * N_ * K;
        const float4* X4 = (const float4*)X;
        constexpr int KQ = K / 4;
        for (int i = t; i < N_ * KQ; i += 512) {
            int r = i / KQ, c = i % KQ;
            uint2 hq, lq;
            split4(X4[i], hq, lq);
            ((uint2*)(Ahi + r * LDA))[c] = hq;
            ((uint2*)(Alo + r * LDA))[c] = lq;
        }
    }
    {
        constexpr int FQ = FO / 8;
        const uint4* GH = (const uint4*)Whi_;
        const uint4* GL = (const uint4*)Wlo_;
        for (int i = t; i < K * FQ; i += 512) {
            int r = i / FQ, c = i % FQ;
            ((uint4*)(Bhi + r * LDB))[c] = GH[i];
            ((uint4*)(Blo + r * LDB))[c] = GL[i];
        }
    }
    for (int i = t; i < E_; i += 512) esm[i] = g_edge[(size_t)g * E_ + i];
    for (int i = t; i < 257; i += 512) rsm[i] = g_rowptr[g * 257 + i];
    for (int i = t; i < 256; i += 512) dsm[i] = g_invdeg[g * N_ + i];
    __syncthreads();

    constexpr int NT = FO / 16;
    wmma::fragment<wmma::accumulator, 16, 16, 16, float> C[NT];
#pragma unroll
    for (int n = 0; n < NT; n++) wmma::fill_fragment(C[n], 0.0f);

    const __nv_bfloat16* Ah = Ahi + (size_t)(wid * 16) * LDA;
    const __nv_bfloat16* Al = Alo + (size_t)(wid * 16) * LDA;
#pragma unroll
    for (int k0 = 0; k0 < K; k0 += 16) {
        wmma::fragment<wmma::matrix_a, 16, 16, 16, __nv_bfloat16, wmma::row_major> ah, al;
        wmma::load_matrix_sync(ah, Ah + k0, LDA);
        wmma::load_matrix_sync(al, Al + k0, LDA);
#pragma unroll
        for (int n = 0; n < NT; n++) {
            wmma::fragment<wmma::matrix_b, 16, 16, 16, __nv_bfloat16, wmma::row_major> bh, bl;
            wmma::load_matrix_sync(bh, Bhi + (size_t)k0 * LDB + n * 16, LDB);
            wmma::load_matrix_sync(bl, Blo + (size_t)k0 * LDB + n * 16, LDB);
            wmma::mma_sync(C[n], ah, bh, C[n]);
            wmma::mma_sync(C[n], ah, bl, C[n]);
            wmma::mma_sync(C[n], al, bh, C[n]);
        }
    }
    __syncthreads();

    float* Hs = (float*)smc;
#pragma unroll
    for (int n = 0; n < NT; n++)
        wmma::store_matrix_sync(Hs + (size_t)(wid * 16) * FO + n * 16, C[n],
                                FO, wmma::mem_row_major);
    __syncthreads();

    constexpr int QPN = FO / 4;
    constexpr int NPB = 512 / QPN;
    const int fq = t % QPN;
    const int n0 = t / QPN;
    const float4 bf = ((const float4*)bias)[fq];
    const float4* h4 = (const float4*)Hs;
    uint2* OHI = (uint2*)g_Xhi + (size_t)g * N_ * QPN;
    uint2* OLO = (uint2*)g_Xlo + (size_t)g * N_ * QPN;

    for (int n = n0; n < N_; n += NPB) {
        const int e0 = rsm[n], e1 = rsm[n + 1];
        float4 a0 = make_float4(0.f, 0.f, 0.f, 0.f);
        float4 a1 = make_float4(0.f, 0.f, 0.f, 0.f);
        int e = e0;
        for (; e + 1 < e1; e += 2) {
            float2 ed0 = esm[e];
            float2 ed1 = esm[e + 1];
            float4 h0 = h4[__float_as_int(ed0.y) * QPN + fq];
            float4 h1 = h4[__float_as_int(ed1.y) * QPN + fq];
            a0.x += h0.x * ed0.x; a0.y += h0.y * ed0.x;
            a0.z += h0.z * ed0.x; a0.w += h0.w * ed0.x;
            a1.x += h1.x * ed1.x; a1.y += h1.y * ed1.x;
            a1.z += h1.z * ed1.x; a1.w += h1.w * ed1.x;
        }
        if (e < e1) {
            float2 ed0 = esm[e];
            float4 h0 = h4[__float_as_int(ed0.y) * QPN + fq];
            a0.x += h0.x * ed0.x; a0.y += h0.y * ed0.x;
            a0.z += h0.z * ed0.x; a0.w += h0.w * ed0.x;
        }
        const float id = dsm[n];
        float4 hs = h4[n * QPN + fq];
        float4 v;
        v.x = fmaxf(a0.x + a1.x + hs.x * id + bf.x, 0.f);
        v.y = fmaxf(a0.y + a1.y + hs.y * id + bf.y, 0.f);
        v.z = fmaxf(a0.z + a1.z + hs.z * id + bf.z, 0.f);
        v.w = fmaxf(a0.w + a1.w + hs.w * id + bf.w, 0.f);
        uint2 hq, lq;
        split4(v, hq, lq);
        OHI[n * QPN + fq] = hq;
        OLO[n * QPN + fq] = lq;
    }
}

// ======================= layers 2+3 + attention pooling, fully smem-resident =======================
// smem map (bytes):
//   [0, 139264)        A-region: A2 hi/lo (LDA2=136); later H2 fp32 [0,64K), A3 hi/lo [64K,137.7K),
//                      H3 fp32 [0,32K), emb fp32 [32K,64K)
//   [139264, 186368)   W-region: W2hi | W2lo | W3hi | W3lo
//   [186368, 202752)   edges (E_ float2)
//   [202752, 203784)   rowptr (258 int)
//   [203784, 204808)   invdeg (256 f)
//   [204808, 208136)   pool scratch: part[512] | colsum[32] | ctx[32] | score[256] = 3328 B
__global__ void __launch_bounds__(512) k_fused23(
    const __nv_bfloat16* __restrict__ W2hi_, const __nv_bfloat16* __restrict__ W2lo_,
    const __nv_bfloat16* __restrict__ W3hi_, const __nv_bfloat16* __restrict__ W3lo_,
    const float* __restrict__ b2, const float* __restrict__ b3,
    const float* __restrict__ Watt)
{
    constexpr int LDA2 = 136, LDB2 = 72, LDA3 = 72, LDB3 = 40;
    extern __shared__ __align__(16) char smc[];
    __nv_bfloat16* A2hi = (__nv_bfloat16*)smc;
    __nv_bfloat16* A2lo = A2hi + 256 * LDA2;
    __nv_bfloat16* W2hi = (__nv_bfloat16*)(smc + 139264);
    __nv_bfloat16* W2lo = W2hi + 128 * LDB2;
    __nv_bfloat16* W3hi = W2lo + 128 * LDB2;
    __nv_bfloat16* W3lo = W3hi + 64 * LDB3;
    float2* esm = (float2*)(smc + 186368);
    int*    rsm = (int*)(smc + 202752);
    float*  dsm = (float*)(smc + 203784);
    float*  part   = (float*)(smc + 204808);   // 512 floats
    float*  colsum = part + 512;
    float*  ctx    = colsum + 32;
    float*  score  = ctx + 32;

    float* H2  = (float*)smc;                          // [0, 64K)
    __nv_bfloat16* A3hi = (__nv_bfloat16*)(smc + 65536);
    __nv_bfloat16* A3lo = A3hi + 256 * LDA3;
    float* H3  = (float*)smc;                          // [0, 32K)
    float* Es  = (float*)(smc + 32768);                // emb fp32 [32K, 64K)

    const int g = blockIdx.x;
    const int t = threadIdx.x;
    const int wid = t >> 5;

    // ---- stage A2 (from layer1 output), W2, W3, edges ----
    {
        const uint4* GH = (const uint4*)(g_Xhi + (size_t)g * N_ * 128);
        const uint4* GL = (const uint4*)(g_Xlo + (size_t)g * N_ * 128);
        for (int i = t; i < N_ * 16; i += 512) {
            int r = i / 16, c = i % 16;
            ((uint4*)(A2hi + r * LDA2))[c] = GH[i];
            ((uint4*)(A2lo + r * LDA2))[c] = GL[i];
        }
    }
    {
        const uint4* GH = (const uint4*)W2hi_;
        const uint4* GL = (const uint4*)W2lo_;
        for (int i = t; i < 128 * 8; i += 512) {
            int r = i / 8, c = i % 8;
            ((uint4*)(W2hi + r * LDB2))[c] = GH[i];
            ((uint4*)(W2lo + r * LDB2))[c] = GL[i];
        }
        const uint4* GH3 = (const uint4*)W3hi_;
        const uint4* GL3 = (const uint4*)W3lo_;
        for (int i = t; i < 64 * 4; i += 512) {
            int r = i / 4, c = i % 4;
            ((uint4*)(W3hi + r * LDB3))[c] = GH3[i];
            ((uint4*)(W3lo + r * LDB3))[c] = GL3[i];
        }
    }
    for (int i = t; i < E_; i += 512) esm[i] = g_edge[(size_t)g * E_ + i];
    for (int i = t; i < 257; i += 512) rsm[i] = g_rowptr[g * 257 + i];
    for (int i = t; i < 256; i += 512) dsm[i] = g_invdeg[g * N_ + i];
    __syncthreads();

    // ======== layer 2 GEMM: 16 warps x 16 rows, FO=64 (NT=4) ========
    {
        wmma::fragment<wmma::accumulator, 16, 16, 16, float> C[4];
#pragma unroll
        for (int n = 0; n < 4; n++) wmma::fill_fragment(C[n], 0.0f);
        const __nv_bfloat16* Ah = A2hi + (size_t)(wid * 16) * LDA2;
        const __nv_bfloat16* Al = A2lo + (size_t)(wid * 16) * LDA2;
#pragma unroll
        for (int k0 = 0; k0 < 128; k0 += 16) {
            wmma::fragment<wmma::matrix_a, 16, 16, 16, __nv_bfloat16, wmma::row_major> ah, al;
            wmma::load_matrix_sync(ah, Ah + k0, LDA2);
            wmma::load_matrix_sync(al, Al + k0, LDA2);
#pragma unroll
            for (int n = 0; n < 4; n++) {
                wmma::fragment<wmma::matrix_b, 16, 16, 16, __nv_bfloat16, wmma::row_major> bh, bl;
                wmma::load_matrix_sync(bh, W2hi + (size_t)k0 * LDB2 + n * 16, LDB2);
                wmma::load_matrix_sync(bl, W2lo + (size_t)k0 * LDB2 + n * 16, LDB2);
                wmma::mma_sync(C[n], ah, bh, C[n]);
                wmma::mma_sync(C[n], ah, bl, C[n]);
                wmma::mma_sync(C[n], al, bh, C[n]);
            }
        }
        __syncthreads();   // A2 reads done -> overlay H2
#pragma unroll
        for (int n = 0; n < 4; n++)
            wmma::store_matrix_sync(H2 + (size_t)(wid * 16) * 64 + n * 16, C[n],
                                    64, wmma::mem_row_major);
        __syncthreads();
    }

    // ======== layer 2 aggregate: H2 -> A3 (bf16 hi/lo, relu) ========
    {
        constexpr int QPN = 16;   // 64/4
        constexpr int NPB = 32;
        const int fq = t % QPN;
        const int n0 = t / QPN;
        const float4 bf = ((const float4*)b2)[fq];
        const float4* h4 = (const float4*)H2;
        for (int n = n0; n < N_; n += NPB) {
            const int e0 = rsm[n], e1 = rsm[n + 1];
            float4 a0 = make_float4(0.f, 0.f, 0.f, 0.f);
            float4 a1 = make_float4(0.f, 0.f, 0.f, 0.f);
            int e = e0;
            for (; e + 1 < e1; e += 2) {
                float2 ed0 = esm[e];
                float2 ed1 = esm[e + 1];
                float4 h0 = h4[__float_as_int(ed0.y) * QPN + fq];
                float4 h1 = h4[__float_as_int(ed1.y) * QPN + fq];
                a0.x += h0.x * ed0.x; a0.y += h0.y * ed0.x;
                a0.z += h0.z * ed0.x; a0.w += h0.w * ed0.x;
                a1.x += h1.x * ed1.x; a1.y += h1.y * ed1.x;
                a1.z += h1.z * ed1.x; a1.w += h1.w * ed1.x;
            }
            if (e < e1) {
                float2 ed0 = esm[e];
                float4 h0 = h4[__float_as_int(ed0.y) * QPN + fq];
                a0.x += h0.x * ed0.x; a0.y += h0.y * ed0.x;
                a0.z += h0.z * ed0.x; a0.w += h0.w * ed0.x;
            }
            const float id = dsm[n];
            float4 hs = h4[n * QPN + fq];
            float4 v;
            v.x = fmaxf(a0.x + a1.x + hs.x * id + bf.x, 0.f);
            v.y = fmaxf(a0.y + a1.y + hs.y * id + bf.y, 0.f);
            v.z = fmaxf(a0.z + a1.z + hs.z * id + bf.z, 0.f);
            v.w = fmaxf(a0.w + a1.w + hs.w * id + bf.w, 0.f);
            uint2 hq, lq;
            split4(v, hq, lq);
            ((uint2*)(A3hi + n * LDA3))[fq] = hq;
            ((uint2*)(A3lo + n * LDA3))[fq] = lq;
        }
        __syncthreads();
    }

    // ======== layer 3 GEMM: K=64, FO=32 (NT=2) ========
    {
        wmma::fragment<wmma::accumulator, 16, 16, 16, float> C[2];
#pragma unroll
        for (int n = 0; n < 2; n++) wmma::fill_fragment(C[n], 0.0f);
        const __nv_bfloat16* Ah = A3hi + (size_t)(wid * 16) * LDA3;
        const __nv_bfloat16* Al = A3lo + (size_t)(wid * 16) * LDA3;
#pragma unroll
        for (int k0 = 0; k0 < 64; k0 += 16) {
            wmma::fragment<wmma::matrix_a, 16, 16, 16, __nv_bfloat16, wmma::row_major> ah, al;
            wmma::load_matrix_sync(ah, Ah + k0, LDA3);
            wmma::load_matrix_sync(al, Al + k0, LDA3);
#pragma unroll
            for (int n = 0; n < 2; n++) {
                wmma::fragment<wmma::matrix_b, 16, 16, 16, __nv_bfloat16, wmma::row_major> bh, bl;
                wmma::load_matrix_sync(bh, W3hi + (size_t)k0 * LDB3 + n * 16, LDB3);
                wmma::load_matrix_sync(bl, W3lo + (size_t)k0 * LDB3 + n * 16, LDB3);
                wmma::mma_sync(C[n], ah, bh, C[n]);
                wmma::mma_sync(C[n], ah, bl, C[n]);
                wmma::mma_sync(C[n], al, bh, C[n]);
            }
        }
        __syncthreads();   // H2 region dead (agg2 done), A3 reads done -> H3 at [0,32K)
#pragma unroll
        for (int n = 0; n < 2; n++)
            wmma::store_matrix_sync(H3 + (size_t)(wid * 16) * 32 + n * 16, C[n],
                                    32, wmma::mem_row_major);
        __syncthreads();
    }

    // ======== layer 3 aggregate: H3 -> emb fp32 (smem) + Phi/Plo (global) ========
    {
        constexpr int QPN = 8;    // 32/4
        constexpr int NPB = 64;
        const int fq = t % QPN;
        const int n0 = t / QPN;
        const float4 bf = ((const float4*)b3)[fq];
        const float4* h4 = (const float4*)H3;
        uint2* PHI = (uint2*)g_Phi + (size_t)g * N_ * QPN;
        uint2* PLO = (uint2*)g_Plo + (size_t)g * N_ * QPN;
        for (int n = n0; n < N_; n += NPB) {
            const int e0 = rsm[n], e1 = rsm[n + 1];
            float4 a0 = make_float4(0.f, 0.f, 0.f, 0.f);
            float4 a1 = make_float4(0.f, 0.f, 0.f, 0.f);
            int e = e0;
            for (; e + 1 < e1; e += 2) {
                float2 ed0 = esm[e];
                float2 ed1 = esm[e + 1];
                float4 h0 = h4[__float_as_int(ed0.y) * QPN + fq];
                float4 h1 = h4[__float_as_int(ed1.y) * QPN + fq];
                a0.x += h0.x * ed0.x; a0.y += h0.y * ed0.x;
                a0.z += h0.z * ed0.x; a0.w += h0.w * ed0.x;
                a1.x += h1.x * ed1.x; a1.y += h1.y * ed1.x;
                a1.z += h1.z * ed1.x; a1.w += h1.w * ed1.x;
            }
            if (e < e1) {
                float2 ed0 = esm[e];
                float4 h0 = h4[__float_as_int(ed0.y) * QPN + fq];
                a0.x += h0.x * ed0.x; a0.y += h0.y * ed0.x;
                a0.z += h0.z * ed0.x; a0.w += h0.w * ed0.x;
            }
            const float id = dsm[n];
            float4 hs = h4[n * QPN + fq];
            float4 v;
            v.x = a0.x + a1.x + hs.x * id + bf.x;
            v.y = a0.y + a1.y + hs.y * id + bf.y;
            v.z = a0.z + a1.z + hs.z * id + bf.z;
            v.w = a0.w + a1.w + hs.w * id + bf.w;
            ((float4*)Es)[n * QPN + fq] = v;
            uint2 hq, lq;
            split4(v, hq, lq);
            PHI[n * QPN + fq] = hq;
            PLO[n * QPN + fq] = lq;
        }
        __syncthreads();
    }

    // ======== attention pooling (parallel two-stage reductions) ========
    {
        // colsum[f] = sum_n Es[n][f]  -- 16 groups x 32 features
        const int f = t & 31, grp = t >> 5;   // 16 warps -> groups
        float s = 0.f;
        for (int n = grp * 16; n < grp * 16 + 16; n++) s += Es[n * 32 + f];
        part[grp * 32 + f] = s;
    }
    __syncthreads();
    if (t < 32) {
        float s = 0.f;
#pragma unroll
        for (int p = 0; p < 16; p++) s += part[p * 32 + t];
        colsum[t] = s;
    }
    __syncthreads();
    if (t < 32) {
        float a = 0.f;
        for (int i = 0; i < 32; i++) a += colsum[i] * Watt[t * 32 + i];
        ctx[t] = tanhf(a * (1.0f / 256.0f));
    }
    __syncthreads();
    if (t < 256) {
        const int lane = t & 31;
        float d = 0.f;
#pragma unroll
        for (int j = 0; j < 32; j++) {
            int i = (lane + j) & 31;
            d += Es[t * 32 + i] * ctx[i];
        }
        score[t] = 1.0f / (1.0f + expf(-d));
    }
    __syncthreads();
    {
        const int f = t & 31, grp = t >> 5;
        float s = 0.f;
        for (int n = grp * 16; n < grp * 16 + 16; n++) s += Es[n * 32 + f] * score[n];
        part[grp * 32 + f] = s;
    }
    __syncthreads();
    if (t < 32) {
        float s = 0.f;
#pragma unroll
        for (int p = 0; p < 16; p++) s += part[p * 32 + t];
        g_pool[g * 32 + t] = s;
    }
}

// ---------------- NTN ----------------
__global__ void __launch_bounds__(512) k_ntn(const float* __restrict__ ntnW,
                                             const float* __restrict__ ntnV,
                                             const float* __restrict__ ntnb) {
    const int b = blockIdx.x;
    __shared__ float e1[32], e2[32];
    const int t = threadIdx.x;
    if (t < 32)      e1[t]      = g_pool[b * 32 + t];
    else if (t < 64) e2[t - 32] = g_pool[(B_ + b) * 32 + (t - 32)];
    __syncthreads();

    const int w = t >> 5, lane = t & 31;
    const float* Wt = ntnW + w * 1024;
    float a = 0.f;
#pragma unroll 8
    for (int j = 0; j < 32; j++) a += Wt[lane * 32 + j] * e2[j];
    float partial = e1[lane] * a
                  + e1[lane] * ntnV[w * 64 + lane]
                  + e2[lane] * ntnV[w * 64 + 32 + lane];
#pragma unroll
    for (int o = 16; o; o >>= 1)
        partial += __shfl_xor_sync(0xffffffffu, partial, o);
    if (lane == 0)
        g_scoresT[b * 16 + w] = fmaxf(partial + ntnb[w], 0.f);
}

// ============ pair matrix: shared staging + split-bf16 wmma tile compute ============
template<typename F>
__device__ __forceinline__ void pair_tiles(int half, int b, int t, F&& consume) {
    constexpr int LD = 40;
    __shared__ __align__(16) __nv_bfloat16 Qh[128 * LD];
    __shared__ __align__(16) __nv_bfloat16 Ql[128 * LD];
    __shared__ __align__(16) __nv_bfloat16 Ch[256 * LD];
    __shared__ __align__(16) __nv_bfloat16 Cl[256 * LD];

    const int wid = t >> 5;

    {
        const uint4* QH = (const uint4*)(g_Phi + ((size_t)b * N_ + half * 128) * 32);
        const uint4* QL = (const uint4*)(g_Plo + ((size_t)b * N_ + half * 128) * 32);
        for (int i = t; i < 128 * 4; i += 256) {
            int r = i / 4, c = i % 4;
            ((uint4*)(Qh + r * LD))[c] = QH[i];
            ((uint4*)(Ql + r * LD))[c] = QL[i];
        }
        const uint4* CH = (const uint4*)(g_Phi + (size_t)(B_ + b) * N_ * 32);
        const uint4* CL = (const uint4*)(g_Plo + (size_t)(B_ + b) * N_ * 32);
        for (int i = t; i < 256 * 4; i += 256) {
            int r = i / 4, c = i % 4;
            ((uint4*)(Ch + r * LD))[c] = CH[i];
            ((uint4*)(Cl + r * LD))[c] = CL[i];
        }
    }
    __syncthreads();

    wmma::fragment<wmma::matrix_a, 16, 16, 16, __nv_bfloat16, wmma::row_major> ah[2], al[2];
#pragma unroll
    for (int kt = 0; kt < 2; kt++) {
        wmma::load_matrix_sync(ah[kt], Qh + (size_t)(wid * 16) * LD + kt * 16, LD);
        wmma::load_matrix_sync(al[kt], Ql + (size_t)(wid * 16) * LD + kt * 16, LD);
    }

#pragma unroll
    for (int ct = 0; ct < 16; ct++) {
        wmma::fragment<wmma::accumulator, 16, 16, 16, float> acc;
        wmma::fill_fragment(acc, 0.0f);
#pragma unroll
        for (int kt = 0; kt < 2; kt++) {
            wmma::fragment<wmma::matrix_b, 16, 16, 16, __nv_bfloat16, wmma::col_major> bh, bl;
            wmma::load_matrix_sync(bh, Ch + (size_t)(ct * 16) * LD + kt * 16, LD);
            wmma::load_matrix_sync(bl, Cl + (size_t)(ct * 16) * LD + kt * 16, LD);
            wmma::mma_sync(acc, ah[kt], bh, acc);
            wmma::mma_sync(acc, ah[kt], bl, acc);
            wmma::mma_sync(acc, al[kt], bh, acc);
        }
        consume(acc);
    }
}

// ---- pass 1: global min/max only ----
__global__ void __launch_bounds__(256) k_pair_minmax() {
    __shared__ float wmn[8], wmx[8];
    const int half = blockIdx.x, b = blockIdx.y;
    const int t = threadIdx.x, wid = t >> 5, lane = t & 31;

    float vmin = 3.402823466e38f, vmax = -3.402823466e38f;
    pair_tiles(half, b, t,
        [&](wmma::fragment<wmma::accumulator, 16, 16, 16, float>& acc) {
#pragma unroll
            for (int i = 0; i < acc.num_elements; i++) {
                vmin = fminf(vmin, acc.x[i]);
                vmax = fmaxf(vmax, acc.x[i]);
            }
        });

#pragma unroll
    for (int o = 16; o; o >>= 1) {
        vmin = fminf(vmin, __shfl_xor_sync(0xffffffffu, vmin, o));
        vmax = fmaxf(vmax, __shfl_xor_sync(0xffffffffu, vmax, o));
    }
    if (lane == 0) { wmn[wid] = vmin; wmx[wid] = vmax; }
    __syncthreads();
    if (t == 0) {
        float m = wmn[0], M = wmx[0];
        for (int i = 1; i < 8; i++) { m = fminf(m, wmn[i]); M = fmaxf(M, wmx[i]); }
        atomicMin(&g_minmax[0], encf(m));
        atomicMax(&g_minmax[1], encf(M));
    }
}

// ---- pass 2: recompute identical tiles, histogram directly ----
__global__ void __launch_bounds__(256) k_pair_hist() {
    __shared__ int hsm[8][16];
    const int half = blockIdx.x, b = blockIdx.y;
    const int t = threadIdx.x, wid = t >> 5;

    if ((t & 31) < 16) hsm[wid][t & 15] = 0;
    __syncthreads();

    const float lo = decf(g_minmax[0]);
    const float inv = 16.0f / (decf(g_minmax[1]) - lo);
    int* myh = hsm[wid];

    pair_tiles(half, b, t,
        [&](wmma::fragment<wmma::accumulator, 16, 16, 16, float>& acc) {
#pragma unroll
            for (int i = 0; i < acc.num_elements; i++) {
                int bi = (int)floorf((acc.x[i] - lo) * inv);
                bi = bi < 0 ? 0 : (bi > 15 ? 15 : bi);
                atomicAdd(&myh[bi], 1);
            }
        });

    __syncthreads();
    if (t < 16) {
        int s = 0;
#pragma unroll
        for (int w = 0; w < 8; w++) s += hsm[w][t];
        atomicAdd(&g_hist[t], s);
    }
}

// ---------------- final MLP head ----------------
__global__ void k_final(const float* __restrict__ fc1W, const float* __restrict__ fc1b,
                        const float* __restrict__ fc2W, const float* __restrict__ fc2b,
                        float* __restrict__ out) {
    __shared__ float h[16];
    const int b = threadIdx.x;
    if (b < 16) h[b] = (float)g_hist[b] * (1.0f / 8388608.0f);
    __syncthreads();

    float sc[16];
#pragma unroll
    for (int t = 0; t < 16; t++) sc[t] = g_scoresT[b * 16 + t];

    float p = fc2b[0];
#pragma unroll
    for (int j = 0; j < 16; j++) {
        float a = fc1b[j];
#pragma unroll
        for (int t = 0; t < 16; t++) a += sc[t] * fc1W[j * 32 + t];
#pragma unroll
        for (int k = 0; k < 16; k++) a += h[k] * fc1W[j * 32 + 16 + k];
        p += fmaxf(a, 0.f) * fc2W[j];
    }
    out[b] = 1.0f / (1.0f + expf(-p));
}

// ---------------- launch ----------------
extern "C" void kernel_launch(void* const* d_in, const int* in_sizes, int n_in,
                              void* d_out, int out_size) {
    const float* xq   = (const float*)d_in[0];
    const float* xc   = (const float*)d_in[1];
    const int*   eq   = (const int*)d_in[2];
    const int*   ec   = (const int*)d_in[3];
    const float* W1   = (const float*)d_in[4];
    const float* b1   = (const float*)d_in[5];
    const float* W2   = (const float*)d_in[6];
    const float* b2   = (const float*)d_in[7];
    const float* W3   = (const float*)d_in[8];
    const float* b3   = (const float*)d_in[9];
    const float* Watt = (const float*)d_in[10];
    const float* ntnW = (const float*)d_in[11];
    const float* ntnV = (const float*)d_in[12];
    const float* ntnb = (const float*)d_in[13];
    const float* fc1W = (const float*)d_in[14];
    const float* fc1b = (const float*)d_in[15];
    const float* fc2W = (const float*)d_in[16];
    const float* fc2b = (const float*)d_in[17];
    float* out = (float*)d_out;

    __nv_bfloat16 *Whi, *Wlo;
    cudaGetSymbolAddress((void**)&Whi, g_Whi);
    cudaGetSymbolAddress((void**)&Wlo, g_Wlo);

    constexpr int EDGE = E_ * 8 + 258 * 4 + 256 * 4;                  // 18,440
    constexpr int SMF1  = (2 * 256 * 136 + 2 * 128 * 136) * 2 + EDGE; // 227,336
    constexpr int SMF23 = 204808 + 3328;                              // 208,136

    cudaFuncSetAttribute(k_fused1,  cudaFuncAttributeMaxDynamicSharedMemorySize, SMF1);
    cudaFuncSetAttribute(k_fused23, cudaFuncAttributeMaxDynamicSharedMemorySize, SMF23);

    k_csr<<<GTOT, 256>>>(eq, ec, W1, W2, W3);

    k_fused1<<<GTOT, 512, SMF1>>>(xq, xc, Whi, Wlo, b1);
    k_fused23<<<GTOT, 512, SMF23>>>(Whi + 16384, Wlo + 16384,
                                    Whi + 24576, Wlo + 24576, b2, b3, Watt);

    k_ntn<<<B_, 512>>>(ntnW, ntnV, ntnb);

    k_pair_minmax<<<dim3(2, B_), 256>>>();
    k_pair_hist<<<dim3(2, B_), 256>>>();

    k_final<<<1, B_>>>(fc1W, fc1b, fc2W, fc2b, out);
}

// round 16
// speedup vs baseline: 1.8789x; 1.0543x over previous
#include <cuda_runtime.h>
#include <cuda_bf16.h>
#include <mma.h>
#include <cstdint>
#include <math.h>

using namespace nvcuda;

#define B_   128
#define N_   256
#define E_   2048
#define GTOT 256   // q graphs [0,128) + c graphs [128,256)

// ---------------- device scratch (static globals: no allocs) ----------------
__device__ __nv_bfloat16 g_Xhi[GTOT * N_ * 128];   // layer1 out hi (128-d)
__device__ __nv_bfloat16 g_Xlo[GTOT * N_ * 128];
__device__ __nv_bfloat16 g_Phi[GTOT * N_ * 32];    // final emb hi (for pair mm)
__device__ __nv_bfloat16 g_Plo[GTOT * N_ * 32];
__device__ __nv_bfloat16 g_Whi[26624];             // W1|W2|W3 bf16 hi
__device__ __nv_bfloat16 g_Wlo[26624];             // W1|W2|W3 bf16 lo
__device__ float2   g_edge[GTOT * E_];         // packed (coef, src-as-float-bits)
__device__ int      g_rowptr[GTOT * 257];
__device__ float    g_invdeg[GTOT * N_];
__device__ float    g_pool[GTOT * 32];
__device__ float    g_scoresT[B_ * 16];
__device__ unsigned g_minmax[2];
__device__ int      g_hist[16];

// monotone float<->uint mapping for atomicMin/Max over signed floats
__device__ __forceinline__ unsigned encf(float f) {
    unsigned u = __float_as_uint(f);
    return (u & 0x80000000u) ? ~u : (u | 0x80000000u);
}
__device__ __forceinline__ float decf(unsigned u) {
    return (u & 0x80000000u) ? __uint_as_float(u & 0x7fffffffu)
                             : __uint_as_float(~u);
}

// pack 4 floats -> (hi uint2, lo uint2) of bf16
__device__ __forceinline__ void split4(float4 v, uint2& hq, uint2& lq) {
    __nv_bfloat16 h0 = __float2bfloat16(v.x);
    __nv_bfloat16 h1 = __float2bfloat16(v.y);
    __nv_bfloat16 h2 = __float2bfloat16(v.z);
    __nv_bfloat16 h3 = __float2bfloat16(v.w);
    __nv_bfloat16 l0 = __float2bfloat16(v.x - __bfloat162float(h0));
    __nv_bfloat16 l1 = __float2bfloat16(v.y - __bfloat162float(h1));
    __nv_bfloat16 l2 = __float2bfloat16(v.z - __bfloat162float(h2));
    __nv_bfloat16 l3 = __float2bfloat16(v.w - __bfloat162float(h3));
    __nv_bfloat162 ph01(h0, h1), ph23(h2, h3), pl01(l0, l1), pl23(l2, l3);
    hq.x = *(unsigned*)&ph01; hq.y = *(unsigned*)&ph23;
    lq.x = *(unsigned*)&pl01; lq.y = *(unsigned*)&pl23;
}

// ---------------- CSR build (per graph) + W conversion + global init ----------------
__global__ void __launch_bounds__(256) k_csr(const int* __restrict__ eq,
                                             const int* __restrict__ ec,
                                             const float* __restrict__ W1,
                                             const float* __restrict__ W2,
                                             const float* __restrict__ W3) {
    const int g = blockIdx.x;
    const int t = threadIdx.x;
    if (g == 0) {
        if (t == 0) { g_minmax[0] = 0xffffffffu; g_minmax[1] = 0u; }
        if (t < 16) g_hist[t] = 0;
    }
    // fold weight conversion into the first 104 blocks
    {
        int wi = g * 256 + t;
        if (wi < 26624) {
            float w = (wi < 16384) ? W1[wi]
                    : (wi < 24576 ? W2[wi - 16384] : W3[wi - 24576]);
            __nv_bfloat16 h = __float2bfloat16(w);
            g_Whi[wi] = h;
            g_Wlo[wi] = __float2bfloat16(w - __bfloat162float(h));
        }
    }
    const int* base = (g < B_) ? (eq + (size_t)g * 2 * E_)
                               : (ec + (size_t)(g - B_) * 2 * E_);
    const int* src = base;
    const int* dst = base + E_;

    __shared__ int   cnt[256];
    __shared__ int   scan[256];
    __shared__ int   off[256];
    __shared__ float dinv[256];

    cnt[t] = 0;
    __syncthreads();
    for (int e = t; e < E_; e += 256) atomicAdd(&cnt[dst[e]], 1);
    __syncthreads();

    float deg = (float)cnt[t] + 1.0f;
    dinv[t] = rsqrtf(deg);
    g_invdeg[g * N_ + t] = 1.0f / deg;

    int v = cnt[t];
    scan[t] = v;
    __syncthreads();
    for (int s = 1; s < 256; s <<= 1) {
        int add = (t >= s) ? scan[t - s] : 0;
        __syncthreads();
        scan[t] += add;
        __syncthreads();
    }
    int excl = scan[t] - v;
    off[t] = excl;
    g_rowptr[g * 257 + t] = excl;
    if (t == 0) g_rowptr[g * 257 + 256] = E_;
    __syncthreads();

    for (int e = t; e < E_; e += 256) {
        int d = dst[e];
        int s_ = src[e];
        int pos = atomicAdd(&off[d], 1);
        g_edge[g * E_ + pos] = make_float2(dinv[s_] * dinv[d], __int_as_float(s_));
    }
}

// ======================= layer 1: stage X -> wmma -> H smem -> gather agg =======================
__global__ void __launch_bounds__(512) k_fused1(
    const float* __restrict__ in0, const float* __restrict__ in1,
    const __nv_bfloat16* __restrict__ Whi_, const __nv_bfloat16* __restrict__ Wlo_,
    const float* __restrict__ bias)
{
    constexpr int K = 128, FO = 128;
    constexpr int LDA = K + 8;
    constexpr int LDB = FO + 8;
    extern __shared__ __align__(16) char smc[];
    __nv_bfloat16* Ahi = (__nv_bfloat16*)smc;          // 256*LDA
    __nv_bfloat16* Alo = Ahi + 256 * LDA;
    __nv_bfloat16* Bhi = Alo + 256 * LDA;              // K*LDB
    __nv_bfloat16* Blo = Bhi + K * LDB;
    float2* esm = (float2*)(Blo + K * LDB);            // E_
    int*    rsm = (int*)(esm + E_);                    // 258
    float*  dsm = (float*)(rsm + 258);                 // 256

    const int g = blockIdx.x;
    const int t = threadIdx.x;
    const int wid = t >> 5;

    {
        const float* X = (g < B_) ? in0 + (size_t)g * N_ * K
                                  : in1 + (size_t)(g - B_) * N_ * K;
        const float4* X4 = (const float4*)X;
        constexpr int KQ = K / 4;
        for (int i = t; i < N_ * KQ; i += 512) {
            int r = i / KQ, c = i % KQ;
            uint2 hq, lq;
            split4(X4[i], hq, lq);
            ((uint2*)(Ahi + r * LDA))[c] = hq;
            ((uint2*)(Alo + r * LDA))[c] = lq;
        }
    }
    {
        constexpr int FQ = FO / 8;
        const uint4* GH = (const uint4*)Whi_;
        const uint4* GL = (const uint4*)Wlo_;
        for (int i = t; i < K * FQ; i += 512) {
            int r = i / FQ, c = i % FQ;
            ((uint4*)(Bhi + r * LDB))[c] = GH[i];
            ((uint4*)(Blo + r * LDB))[c] = GL[i];
        }
    }
    for (int i = t; i < E_; i += 512) esm[i] = g_edge[(size_t)g * E_ + i];
    for (int i = t; i < 257; i += 512) rsm[i] = g_rowptr[g * 257 + i];
    for (int i = t; i < 256; i += 512) dsm[i] = g_invdeg[g * N_ + i];
    __syncthreads();

    constexpr int NT = FO / 16;
    wmma::fragment<wmma::accumulator, 16, 16, 16, float> C[NT];
#pragma unroll
    for (int n = 0; n < NT; n++) wmma::fill_fragment(C[n], 0.0f);

    const __nv_bfloat16* Ah = Ahi + (size_t)(wid * 16) * LDA;
    const __nv_bfloat16* Al = Alo + (size_t)(wid * 16) * LDA;
#pragma unroll
    for (int k0 = 0; k0 < K; k0 += 16) {
        wmma::fragment<wmma::matrix_a, 16, 16, 16, __nv_bfloat16, wmma::row_major> ah, al;
        wmma::load_matrix_sync(ah, Ah + k0, LDA);
        wmma::load_matrix_sync(al, Al + k0, LDA);
#pragma unroll
        for (int n = 0; n < NT; n++) {
            wmma::fragment<wmma::matrix_b, 16, 16, 16, __nv_bfloat16, wmma::row_major> bh, bl;
            wmma::load_matrix_sync(bh, Bhi + (size_t)k0 * LDB + n * 16, LDB);
            wmma::load_matrix_sync(bl, Blo + (size_t)k0 * LDB + n * 16, LDB);
            wmma::mma_sync(C[n], ah, bh, C[n]);
            wmma::mma_sync(C[n], ah, bl, C[n]);
            wmma::mma_sync(C[n], al, bh, C[n]);
        }
    }
    __syncthreads();

    float* Hs = (float*)smc;
#pragma unroll
    for (int n = 0; n < NT; n++)
        wmma::store_matrix_sync(Hs + (size_t)(wid * 16) * FO + n * 16, C[n],
                                FO, wmma::mem_row_major);
    __syncthreads();

    constexpr int QPN = FO / 4;
    constexpr int NPB = 512 / QPN;
    const int fq = t % QPN;
    const int n0 = t / QPN;
    const float4 bf = ((const float4*)bias)[fq];
    const float4* h4 = (const float4*)Hs;
    uint2* OHI = (uint2*)g_Xhi + (size_t)g * N_ * QPN;
    uint2* OLO = (uint2*)g_Xlo + (size_t)g * N_ * QPN;

    for (int n = n0; n < N_; n += NPB) {
        const int e0 = rsm[n], e1 = rsm[n + 1];
        float4 a0 = make_float4(0.f, 0.f, 0.f, 0.f);
        float4 a1 = make_float4(0.f, 0.f, 0.f, 0.f);
        int e = e0;
        for (; e + 1 < e1; e += 2) {
            float2 ed0 = esm[e];
            float2 ed1 = esm[e + 1];
            float4 h0 = h4[__float_as_int(ed0.y) * QPN + fq];
            float4 h1 = h4[__float_as_int(ed1.y) * QPN + fq];
            a0.x += h0.x * ed0.x; a0.y += h0.y * ed0.x;
            a0.z += h0.z * ed0.x; a0.w += h0.w * ed0.x;
            a1.x += h1.x * ed1.x; a1.y += h1.y * ed1.x;
            a1.z += h1.z * ed1.x; a1.w += h1.w * ed1.x;
        }
        if (e < e1) {
            float2 ed0 = esm[e];
            float4 h0 = h4[__float_as_int(ed0.y) * QPN + fq];
            a0.x += h0.x * ed0.x; a0.y += h0.y * ed0.x;
            a0.z += h0.z * ed0.x; a0.w += h0.w * ed0.x;
        }
        const float id = dsm[n];
        float4 hs = h4[n * QPN + fq];
        float4 v;
        v.x = fmaxf(a0.x + a1.x + hs.x * id + bf.x, 0.f);
        v.y = fmaxf(a0.y + a1.y + hs.y * id + bf.y, 0.f);
        v.z = fmaxf(a0.z + a1.z + hs.z * id + bf.z, 0.f);
        v.w = fmaxf(a0.w + a1.w + hs.w * id + bf.w, 0.f);
        uint2 hq, lq;
        split4(v, hq, lq);
        OHI[n * QPN + fq] = hq;
        OLO[n * QPN + fq] = lq;
    }
}

// ======================= layers 2+3 + attention pooling, fully smem-resident =======================
__global__ void __launch_bounds__(512) k_fused23(
    const __nv_bfloat16* __restrict__ W2hi_, const __nv_bfloat16* __restrict__ W2lo_,
    const __nv_bfloat16* __restrict__ W3hi_, const __nv_bfloat16* __restrict__ W3lo_,
    const float* __restrict__ b2, const float* __restrict__ b3,
    const float* __restrict__ Watt)
{
    constexpr int LDA2 = 136, LDB2 = 72, LDA3 = 72, LDB3 = 40;
    extern __shared__ __align__(16) char smc[];
    __nv_bfloat16* A2hi = (__nv_bfloat16*)smc;
    __nv_bfloat16* A2lo = A2hi + 256 * LDA2;
    __nv_bfloat16* W2hi = (__nv_bfloat16*)(smc + 139264);
    __nv_bfloat16* W2lo = W2hi + 128 * LDB2;
    __nv_bfloat16* W3hi = W2lo + 128 * LDB2;
    __nv_bfloat16* W3lo = W3hi + 64 * LDB3;
    float2* esm = (float2*)(smc + 186368);
    int*    rsm = (int*)(smc + 202752);
    float*  dsm = (float*)(smc + 203784);
    float*  part   = (float*)(smc + 204808);   // 512 floats
    float*  colsum = part + 512;
    float*  ctx    = colsum + 32;
    float*  score  = ctx + 32;

    float* H2  = (float*)smc;                          // [0, 64K)
    __nv_bfloat16* A3hi = (__nv_bfloat16*)(smc + 65536);
    __nv_bfloat16* A3lo = A3hi + 256 * LDA3;
    float* H3  = (float*)smc;                          // [0, 32K)
    float* Es  = (float*)(smc + 32768);                // emb fp32 [32K, 64K)

    const int g = blockIdx.x;
    const int t = threadIdx.x;
    const int wid = t >> 5;

    // ---- stage A2 (from layer1 output), W2, W3, edges ----
    {
        const uint4* GH = (const uint4*)(g_Xhi + (size_t)g * N_ * 128);
        const uint4* GL = (const uint4*)(g_Xlo + (size_t)g * N_ * 128);
        for (int i = t; i < N_ * 16; i += 512) {
            int r = i / 16, c = i % 16;
            ((uint4*)(A2hi + r * LDA2))[c] = GH[i];
            ((uint4*)(A2lo + r * LDA2))[c] = GL[i];
        }
    }
    {
        const uint4* GH = (const uint4*)W2hi_;
        const uint4* GL = (const uint4*)W2lo_;
        for (int i = t; i < 128 * 8; i += 512) {
            int r = i / 8, c = i % 8;
            ((uint4*)(W2hi + r * LDB2))[c] = GH[i];
            ((uint4*)(W2lo + r * LDB2))[c] = GL[i];
        }
        const uint4* GH3 = (const uint4*)W3hi_;
        const uint4* GL3 = (const uint4*)W3lo_;
        for (int i = t; i < 64 * 4; i += 512) {
            int r = i / 4, c = i % 4;
            ((uint4*)(W3hi + r * LDB3))[c] = GH3[i];
            ((uint4*)(W3lo + r * LDB3))[c] = GL3[i];
        }
    }
    for (int i = t; i < E_; i += 512) esm[i] = g_edge[(size_t)g * E_ + i];
    for (int i = t; i < 257; i += 512) rsm[i] = g_rowptr[g * 257 + i];
    for (int i = t; i < 256; i += 512) dsm[i] = g_invdeg[g * N_ + i];
    __syncthreads();

    // ======== layer 2 GEMM: 16 warps x 16 rows, FO=64 (NT=4) ========
    {
        wmma::fragment<wmma::accumulator, 16, 16, 16, float> C[4];
#pragma unroll
        for (int n = 0; n < 4; n++) wmma::fill_fragment(C[n], 0.0f);
        const __nv_bfloat16* Ah = A2hi + (size_t)(wid * 16) * LDA2;
        const __nv_bfloat16* Al = A2lo + (size_t)(wid * 16) * LDA2;
#pragma unroll
        for (int k0 = 0; k0 < 128; k0 += 16) {
            wmma::fragment<wmma::matrix_a, 16, 16, 16, __nv_bfloat16, wmma::row_major> ah, al;
            wmma::load_matrix_sync(ah, Ah + k0, LDA2);
            wmma::load_matrix_sync(al, Al + k0, LDA2);
#pragma unroll
            for (int n = 0; n < 4; n++) {
                wmma::fragment<wmma::matrix_b, 16, 16, 16, __nv_bfloat16, wmma::row_major> bh, bl;
                wmma::load_matrix_sync(bh, W2hi + (size_t)k0 * LDB2 + n * 16, LDB2);
                wmma::load_matrix_sync(bl, W2lo + (size_t)k0 * LDB2 + n * 16, LDB2);
                wmma::mma_sync(C[n], ah, bh, C[n]);
                wmma::mma_sync(C[n], ah, bl, C[n]);
                wmma::mma_sync(C[n], al, bh, C[n]);
            }
        }
        __syncthreads();   // A2 reads done -> overlay H2
#pragma unroll
        for (int n = 0; n < 4; n++)
            wmma::store_matrix_sync(H2 + (size_t)(wid * 16) * 64 + n * 16, C[n],
                                    64, wmma::mem_row_major);
        __syncthreads();
    }

    // ======== layer 2 aggregate: H2 -> A3 (bf16 hi/lo, relu) ========
    {
        constexpr int QPN = 16;   // 64/4
        constexpr int NPB = 32;
        const int fq = t % QPN;
        const int n0 = t / QPN;
        const float4 bf = ((const float4*)b2)[fq];
        const float4* h4 = (const float4*)H2;
        for (int n = n0; n < N_; n += NPB) {
            const int e0 = rsm[n], e1 = rsm[n + 1];
            float4 a0 = make_float4(0.f, 0.f, 0.f, 0.f);
            float4 a1 = make_float4(0.f, 0.f, 0.f, 0.f);
            int e = e0;
            for (; e + 1 < e1; e += 2) {
                float2 ed0 = esm[e];
                float2 ed1 = esm[e + 1];
                float4 h0 = h4[__float_as_int(ed0.y) * QPN + fq];
                float4 h1 = h4[__float_as_int(ed1.y) * QPN + fq];
                a0.x += h0.x * ed0.x; a0.y += h0.y * ed0.x;
                a0.z += h0.z * ed0.x; a0.w += h0.w * ed0.x;
                a1.x += h1.x * ed1.x; a1.y += h1.y * ed1.x;
                a1.z += h1.z * ed1.x; a1.w += h1.w * ed1.x;
            }
            if (e < e1) {
                float2 ed0 = esm[e];
                float4 h0 = h4[__float_as_int(ed0.y) * QPN + fq];
                a0.x += h0.x * ed0.x; a0.y += h0.y * ed0.x;
                a0.z += h0.z * ed0.x; a0.w += h0.w * ed0.x;
            }
            const float id = dsm[n];
            float4 hs = h4[n * QPN + fq];
            float4 v;
            v.x = fmaxf(a0.x + a1.x + hs.x * id + bf.x, 0.f);
            v.y = fmaxf(a0.y + a1.y + hs.y * id + bf.y, 0.f);
            v.z = fmaxf(a0.z + a1.z + hs.z * id + bf.z, 0.f);
            v.w = fmaxf(a0.w + a1.w + hs.w * id + bf.w, 0.f);
            uint2 hq, lq;
            split4(v, hq, lq);
            ((uint2*)(A3hi + n * LDA3))[fq] = hq;
            ((uint2*)(A3lo + n * LDA3))[fq] = lq;
        }
        __syncthreads();
    }

    // ======== layer 3 GEMM: K=64, FO=32 (NT=2) ========
    {
        wmma::fragment<wmma::accumulator, 16, 16, 16, float> C[2];
#pragma unroll
        for (int n = 0; n < 2; n++) wmma::fill_fragment(C[n], 0.0f);
        const __nv_bfloat16* Ah = A3hi + (size_t)(wid * 16) * LDA3;
        const __nv_bfloat16* Al = A3lo + (size_t)(wid * 16) * LDA3;
#pragma unroll
        for (int k0 = 0; k0 < 64; k0 += 16) {
            wmma::fragment<wmma::matrix_a, 16, 16, 16, __nv_bfloat16, wmma::row_major> ah, al;
            wmma::load_matrix_sync(ah, Ah + k0, LDA3);
            wmma::load_matrix_sync(al, Al + k0, LDA3);
#pragma unroll
            for (int n = 0; n < 2; n++) {
                wmma::fragment<wmma::matrix_b, 16, 16, 16, __nv_bfloat16, wmma::row_major> bh, bl;
                wmma::load_matrix_sync(bh, W3hi + (size_t)k0 * LDB3 + n * 16, LDB3);
                wmma::load_matrix_sync(bl, W3lo + (size_t)k0 * LDB3 + n * 16, LDB3);
                wmma::mma_sync(C[n], ah, bh, C[n]);
                wmma::mma_sync(C[n], ah, bl, C[n]);
                wmma::mma_sync(C[n], al, bh, C[n]);
            }
        }
        __syncthreads();   // H2 region dead (agg2 done), A3 reads done -> H3 at [0,32K)
#pragma unroll
        for (int n = 0; n < 2; n++)
            wmma::store_matrix_sync(H3 + (size_t)(wid * 16) * 32 + n * 16, C[n],
                                    32, wmma::mem_row_major);
        __syncthreads();
    }

    // ======== layer 3 aggregate: H3 -> emb fp32 (smem) + Phi/Plo (global) ========
    {
        constexpr int QPN = 8;    // 32/4
        constexpr int NPB = 64;
        const int fq = t % QPN;
        const int n0 = t / QPN;
        const float4 bf = ((const float4*)b3)[fq];
        const float4* h4 = (const float4*)H3;
        uint2* PHI = (uint2*)g_Phi + (size_t)g * N_ * QPN;
        uint2* PLO = (uint2*)g_Plo + (size_t)g * N_ * QPN;
        for (int n = n0; n < N_; n += NPB) {
            const int e0 = rsm[n], e1 = rsm[n + 1];
            float4 a0 = make_float4(0.f, 0.f, 0.f, 0.f);
            float4 a1 = make_float4(0.f, 0.f, 0.f, 0.f);
            int e = e0;
            for (; e + 1 < e1; e += 2) {
                float2 ed0 = esm[e];
                float2 ed1 = esm[e + 1];
                float4 h0 = h4[__float_as_int(ed0.y) * QPN + fq];
                float4 h1 = h4[__float_as_int(ed1.y) * QPN + fq];
                a0.x += h0.x * ed0.x; a0.y += h0.y * ed0.x;
                a0.z += h0.z * ed0.x; a0.w += h0.w * ed0.x;
                a1.x += h1.x * ed1.x; a1.y += h1.y * ed1.x;
                a1.z += h1.z * ed1.x; a1.w += h1.w * ed1.x;
            }
            if (e < e1) {
                float2 ed0 = esm[e];
                float4 h0 = h4[__float_as_int(ed0.y) * QPN + fq];
                a0.x += h0.x * ed0.x; a0.y += h0.y * ed0.x;
                a0.z += h0.z * ed0.x; a0.w += h0.w * ed0.x;
            }
            const float id = dsm[n];
            float4 hs = h4[n * QPN + fq];
            float4 v;
            v.x = a0.x + a1.x + hs.x * id + bf.x;
            v.y = a0.y + a1.y + hs.y * id + bf.y;
            v.z = a0.z + a1.z + hs.z * id + bf.z;
            v.w = a0.w + a1.w + hs.w * id + bf.w;
            ((float4*)Es)[n * QPN + fq] = v;
            uint2 hq, lq;
            split4(v, hq, lq);
            PHI[n * QPN + fq] = hq;
            PLO[n * QPN + fq] = lq;
        }
        __syncthreads();
    }

    // ======== attention pooling (parallel two-stage reductions) ========
    {
        const int f = t & 31, grp = t >> 5;   // 16 warps -> groups
        float s = 0.f;
        for (int n = grp * 16; n < grp * 16 + 16; n++) s += Es[n * 32 + f];
        part[grp * 32 + f] = s;
    }
    __syncthreads();
    if (t < 32) {
        float s = 0.f;
#pragma unroll
        for (int p = 0; p < 16; p++) s += part[p * 32 + t];
        colsum[t] = s;
    }
    __syncthreads();
    if (t < 32) {
        float a = 0.f;
        for (int i = 0; i < 32; i++) a += colsum[i] * Watt[t * 32 + i];
        ctx[t] = tanhf(a * (1.0f / 256.0f));
    }
    __syncthreads();
    if (t < 256) {
        const int lane = t & 31;
        float d = 0.f;
#pragma unroll
        for (int j = 0; j < 32; j++) {
            int i = (lane + j) & 31;
            d += Es[t * 32 + i] * ctx[i];
        }
        score[t] = 1.0f / (1.0f + expf(-d));
    }
    __syncthreads();
    {
        const int f = t & 31, grp = t >> 5;
        float s = 0.f;
        for (int n = grp * 16; n < grp * 16 + 16; n++) s += Es[n * 32 + f] * score[n];
        part[grp * 32 + f] = s;
    }
    __syncthreads();
    if (t < 32) {
        float s = 0.f;
#pragma unroll
        for (int p = 0; p < 16; p++) s += part[p * 32 + t];
        g_pool[g * 32 + t] = s;
    }
}

// ============ pair matrix: shared staging + split-bf16 wmma tile compute ============
template<typename F>
__device__ __forceinline__ void pair_tiles(int half, int b, int t, F&& consume) {
    constexpr int LD = 40;
    __shared__ __align__(16) __nv_bfloat16 Qh[128 * LD];
    __shared__ __align__(16) __nv_bfloat16 Ql[128 * LD];
    __shared__ __align__(16) __nv_bfloat16 Ch[256 * LD];
    __shared__ __align__(16) __nv_bfloat16 Cl[256 * LD];

    const int wid = t >> 5;

    {
        const uint4* QH = (const uint4*)(g_Phi + ((size_t)b * N_ + half * 128) * 32);
        const uint4* QL = (const uint4*)(g_Plo + ((size_t)b * N_ + half * 128) * 32);
        for (int i = t; i < 128 * 4; i += 256) {
            int r = i / 4, c = i % 4;
            ((uint4*)(Qh + r * LD))[c] = QH[i];
            ((uint4*)(Ql + r * LD))[c] = QL[i];
        }
        const uint4* CH = (const uint4*)(g_Phi + (size_t)(B_ + b) * N_ * 32);
        const uint4* CL = (const uint4*)(g_Plo + (size_t)(B_ + b) * N_ * 32);
        for (int i = t; i < 256 * 4; i += 256) {
            int r = i / 4, c = i % 4;
            ((uint4*)(Ch + r * LD))[c] = CH[i];
            ((uint4*)(Cl + r * LD))[c] = CL[i];
        }
    }
    __syncthreads();

    wmma::fragment<wmma::matrix_a, 16, 16, 16, __nv_bfloat16, wmma::row_major> ah[2], al[2];
#pragma unroll
    for (int kt = 0; kt < 2; kt++) {
        wmma::load_matrix_sync(ah[kt], Qh + (size_t)(wid * 16) * LD + kt * 16, LD);
        wmma::load_matrix_sync(al[kt], Ql + (size_t)(wid * 16) * LD + kt * 16, LD);
    }

#pragma unroll
    for (int ct = 0; ct < 16; ct++) {
        wmma::fragment<wmma::accumulator, 16, 16, 16, float> acc;
        wmma::fill_fragment(acc, 0.0f);
#pragma unroll
        for (int kt = 0; kt < 2; kt++) {
            wmma::fragment<wmma::matrix_b, 16, 16, 16, __nv_bfloat16, wmma::col_major> bh, bl;
            wmma::load_matrix_sync(bh, Ch + (size_t)(ct * 16) * LD + kt * 16, LD);
            wmma::load_matrix_sync(bl, Cl + (size_t)(ct * 16) * LD + kt * 16, LD);
            wmma::mma_sync(acc, ah[kt], bh, acc);
            wmma::mma_sync(acc, ah[kt], bl, acc);
            wmma::mma_sync(acc, al[kt], bh, acc);
        }
        consume(acc);
    }
}

// ---- pass 1: global min/max (x<2) + NTN folded in (x==2) ----
__global__ void __launch_bounds__(256) k_pair_minmax(
    const float* __restrict__ ntnW, const float* __restrict__ ntnV,
    const float* __restrict__ ntnb) {
    const int t = threadIdx.x, wid = t >> 5, lane = t & 31;
    const int b = blockIdx.y;

    if (blockIdx.x == 2) {
        // ---------- NTN for batch b (8 warps x 2 neurons) ----------
        __shared__ float e1[32], e2[32];
        if (t < 32)      e1[t]      = g_pool[b * 32 + t];
        else if (t < 64) e2[t - 32] = g_pool[(B_ + b) * 32 + (t - 32)];
        __syncthreads();
#pragma unroll
        for (int nn = wid; nn < 16; nn += 8) {
            const float4* Wt = (const float4*)(ntnW + nn * 1024 + lane * 32);
            float a = 0.f;
#pragma unroll
            for (int j = 0; j < 8; j++) {
                float4 wv = Wt[j];
                a += wv.x * e2[j * 4] + wv.y * e2[j * 4 + 1]
                   + wv.z * e2[j * 4 + 2] + wv.w * e2[j * 4 + 3];
            }
            float partial = e1[lane] * a
                          + e1[lane] * ntnV[nn * 64 + lane]
                          + e2[lane] * ntnV[nn * 64 + 32 + lane];
#pragma unroll
            for (int o = 16; o; o >>= 1)
                partial += __shfl_xor_sync(0xffffffffu, partial, o);
            if (lane == 0)
                g_scoresT[b * 16 + nn] = fmaxf(partial + ntnb[nn], 0.f);
        }
        return;
    }

    __shared__ float wmn[8], wmx[8];
    const int half = blockIdx.x;

    float vmin = 3.402823466e38f, vmax = -3.402823466e38f;
    pair_tiles(half, b, t,
        [&](wmma::fragment<wmma::accumulator, 16, 16, 16, float>& acc) {
#pragma unroll
            for (int i = 0; i < acc.num_elements; i++) {
                vmin = fminf(vmin, acc.x[i]);
                vmax = fmaxf(vmax, acc.x[i]);
            }
        });

#pragma unroll
    for (int o = 16; o; o >>= 1) {
        vmin = fminf(vmin, __shfl_xor_sync(0xffffffffu, vmin, o));
        vmax = fmaxf(vmax, __shfl_xor_sync(0xffffffffu, vmax, o));
    }
    if (lane == 0) { wmn[wid] = vmin; wmx[wid] = vmax; }
    __syncthreads();
    if (t == 0) {
        float m = wmn[0], M = wmx[0];
        for (int i = 1; i < 8; i++) { m = fminf(m, wmn[i]); M = fmaxf(M, wmx[i]); }
        atomicMin(&g_minmax[0], encf(m));
        atomicMax(&g_minmax[1], encf(M));
    }
}

// ---- pass 2: recompute identical tiles, histogram directly ----
__global__ void __launch_bounds__(256) k_pair_hist() {
    __shared__ int hsm[8][16];
    const int half = blockIdx.x, b = blockIdx.y;
    const int t = threadIdx.x, wid = t >> 5;

    if ((t & 31) < 16) hsm[wid][t & 15] = 0;
    __syncthreads();

    const float lo = decf(g_minmax[0]);
    const float inv = 16.0f / (decf(g_minmax[1]) - lo);
    int* myh = hsm[wid];

    pair_tiles(half, b, t,
        [&](wmma::fragment<wmma::accumulator, 16, 16, 16, float>& acc) {
#pragma unroll
            for (int i = 0; i < acc.num_elements; i++) {
                int bi = (int)floorf((acc.x[i] - lo) * inv);
                bi = bi < 0 ? 0 : (bi > 15 ? 15 : bi);
                atomicAdd(&myh[bi], 1);
            }
        });

    __syncthreads();
    if (t < 16) {
        int s = 0;
#pragma unroll
        for (int w = 0; w < 8; w++) s += hsm[w][t];
        atomicAdd(&g_hist[t], s);
    }
}

// ---------------- final MLP head ----------------
__global__ void k_final(const float* __restrict__ fc1W, const float* __restrict__ fc1b,
                        const float* __restrict__ fc2W, const float* __restrict__ fc2b,
                        float* __restrict__ out) {
    __shared__ float h[16];
    const int b = threadIdx.x;
    if (b < 16) h[b] = (float)g_hist[b] * (1.0f / 8388608.0f);
    __syncthreads();

    float sc[16];
#pragma unroll
    for (int t = 0; t < 16; t++) sc[t] = g_scoresT[b * 16 + t];

    float p = fc2b[0];
#pragma unroll
    for (int j = 0; j < 16; j++) {
        float a = fc1b[j];
#pragma unroll
        for (int t = 0; t < 16; t++) a += sc[t] * fc1W[j * 32 + t];
#pragma unroll
        for (int k = 0; k < 16; k++) a += h[k] * fc1W[j * 32 + 16 + k];
        p += fmaxf(a, 0.f) * fc2W[j];
    }
    out[b] = 1.0f / (1.0f + expf(-p));
}

// ---------------- launch ----------------
extern "C" void kernel_launch(void* const* d_in, const int* in_sizes, int n_in,
                              void* d_out, int out_size) {
    const float* xq   = (const float*)d_in[0];
    const float* xc   = (const float*)d_in[1];
    const int*   eq   = (const int*)d_in[2];
    const int*   ec   = (const int*)d_in[3];
    const float* W1   = (const float*)d_in[4];
    const float* b1   = (const float*)d_in[5];
    const float* W2   = (const float*)d_in[6];
    const float* b2   = (const float*)d_in[7];
    const float* W3   = (const float*)d_in[8];
    const float* b3   = (const float*)d_in[9];
    const float* Watt = (const float*)d_in[10];
    const float* ntnW = (const float*)d_in[11];
    const float* ntnV = (const float*)d_in[12];
    const float* ntnb = (const float*)d_in[13];
    const float* fc1W = (const float*)d_in[14];
    const float* fc1b = (const float*)d_in[15];
    const float* fc2W = (const float*)d_in[16];
    const float* fc2b = (const float*)d_in[17];
    float* out = (float*)d_out;

    __nv_bfloat16 *Whi, *Wlo;
    cudaGetSymbolAddress((void**)&Whi, g_Whi);
    cudaGetSymbolAddress((void**)&Wlo, g_Wlo);

    constexpr int EDGE = E_ * 8 + 258 * 4 + 256 * 4;                  // 18,440
    constexpr int SMF1  = (2 * 256 * 136 + 2 * 128 * 136) * 2 + EDGE; // 227,336
    constexpr int SMF23 = 204808 + 3328;                              // 208,136

    cudaFuncSetAttribute(k_fused1,  cudaFuncAttributeMaxDynamicSharedMemorySize, SMF1);
    cudaFuncSetAttribute(k_fused23, cudaFuncAttributeMaxDynamicSharedMemorySize, SMF23);

    k_csr<<<GTOT, 256>>>(eq, ec, W1, W2, W3);

    k_fused1<<<GTOT, 512, SMF1>>>(xq, xc, Whi, Wlo, b1);
    k_fused23<<<GTOT, 512, SMF23>>>(Whi + 16384, Wlo + 16384,
                                    Whi + 24576, Wlo + 24576, b2, b3, Watt);

    k_pair_minmax<<<dim3(3, B_), 256>>>(ntnW, ntnV, ntnb);
    k_pair_hist<<<dim3(2, B_), 256>>>();

    k_final<<<1, B_>>>(fc1W, fc1b, fc2W, fc2b, out);
}